// round 7
// baseline (speedup 1.0000x reference)
#include <cuda_runtime.h>
#include <cuda_bf16.h>
#include <cuda_fp16.h>
#include <math.h>
#include <stdint.h>

// Problem constants
#define BB 2
#define SS 2048
#define DIN 1024
#define HH 16
#define DKK 1024
#define DVV 1024
#define DOUT 1024
#define MROWS (BB*SS)          // 4096
#define BH (BB*HH)             // 32
#define HEADV 64
#define SCALE 0.125f
#define LN_EPS 1e-5f

// Scratch
__device__ float g_q  [(size_t)MROWS * DKK];
__device__ float g_k  [(size_t)MROWS * DKK];
__device__ float g_v  [(size_t)MROWS * DVV];
__device__ float g_ctx[(size_t)MROWS * DVV];
__device__ float g_res[(size_t)MROWS * DOUT];
__device__ float g_cb [(size_t)MROWS * HH];
__device__ float g_cbt[(size_t)BH * SS];
__device__ float g_scores[(size_t)BH * SS * SS];            // 536 MB
__device__ __half g_qh[(size_t)BH * SS * DKK];              // fp16 hi
__device__ __half g_ql[(size_t)BH * SS * DKK];              // fp16 lo
__device__ __half g_kf[(size_t)MROWS * DKK];                // fp16 single
__device__ __nv_bfloat16 g_xh[(size_t)MROWS * DIN];
__device__ __nv_bfloat16 g_xl[(size_t)MROWS * DIN];
__device__ __nv_bfloat16 g_wh[(size_t)4 * 1024 * 1024];
__device__ __nv_bfloat16 g_wl[(size_t)4 * 1024 * 1024];
__device__ __nv_bfloat16 g_vth[(size_t)BH * HEADV * SS];
__device__ __nv_bfloat16 g_vtl[(size_t)BH * HEADV * SS];
__device__ __nv_bfloat16 g_cxh[(size_t)MROWS * DVV];
__device__ __nv_bfloat16 g_cxl[(size_t)MROWS * DVV];

// ======================= helpers ===========================================
__device__ __forceinline__ uint32_t smem_to_u32(const void* p) {
    uint32_t a;
    asm("{ .reg .u64 t; cvta.to.shared.u64 t, %1; cvt.u32.u64 %0, t; }" : "=r"(a) : "l"(p));
    return a;
}
__device__ __forceinline__ void cp16(uint32_t s, const void* g) {
    asm volatile("cp.async.cg.shared.global [%0], [%1], 16;" :: "r"(s), "l"(g));
}
#define CP_COMMIT() asm volatile("cp.async.commit_group;" ::: "memory")
#define CP_WAIT1()  asm volatile("cp.async.wait_group 1;" ::: "memory")
#define CP_WAIT0()  asm volatile("cp.async.wait_group 0;" ::: "memory")

__device__ __forceinline__ void ldsm_x4(uint32_t* r, uint32_t addr) {
    asm volatile("ldmatrix.sync.aligned.m8n8.x4.shared.b16 {%0,%1,%2,%3}, [%4];"
        : "=r"(r[0]), "=r"(r[1]), "=r"(r[2]), "=r"(r[3]) : "r"(addr));
}
__device__ __forceinline__ void ldsm_x2(uint32_t* r, uint32_t addr) {
    asm volatile("ldmatrix.sync.aligned.m8n8.x2.shared.b16 {%0,%1}, [%2];"
        : "=r"(r[0]), "=r"(r[1]) : "r"(addr));
}
__device__ __forceinline__ void mma_bf16(float* c, const uint32_t* a, const uint32_t* b) {
    asm volatile("mma.sync.aligned.m16n8k16.row.col.f32.bf16.bf16.f32 "
        "{%0,%1,%2,%3}, {%4,%5,%6,%7}, {%8,%9}, {%0,%1,%2,%3};"
        : "+f"(c[0]), "+f"(c[1]), "+f"(c[2]), "+f"(c[3])
        : "r"(a[0]), "r"(a[1]), "r"(a[2]), "r"(a[3]), "r"(b[0]), "r"(b[1]));
}
__device__ __forceinline__ void mma_fp16(float* c, const uint32_t* a, const uint32_t* b) {
    asm volatile("mma.sync.aligned.m16n8k16.row.col.f32.f16.f16.f32 "
        "{%0,%1,%2,%3}, {%4,%5,%6,%7}, {%8,%9}, {%0,%1,%2,%3};"
        : "+f"(c[0]), "+f"(c[1]), "+f"(c[2]), "+f"(c[3])
        : "r"(a[0]), "r"(a[1]), "r"(a[2]), "r"(a[3]), "r"(b[0]), "r"(b[1]));
}
__device__ __forceinline__ uint32_t pack2(__nv_bfloat16 a, __nv_bfloat16 b) {
    return (uint32_t)__bfloat16_as_ushort(a) | ((uint32_t)__bfloat16_as_ushort(b) << 16);
}
__device__ __forceinline__ uint32_t pack2h(__half a, __half b) {
    return (uint32_t)__half_as_ushort(a) | ((uint32_t)__half_as_ushort(b) << 16);
}

// ======================= generic fp32 -> bf16 hi/lo split ==================
__global__ __launch_bounds__(256)
void split_kernel(const float* __restrict__ in,
                  __nv_bfloat16* __restrict__ h, __nv_bfloat16* __restrict__ l)
{
    const size_t i4 = (size_t)blockIdx.x * 256 + threadIdx.x;
    float4 v = *(const float4*)(in + i4 * 4);
    __nv_bfloat16 h0 = __float2bfloat16(v.x), h1 = __float2bfloat16(v.y);
    __nv_bfloat16 h2 = __float2bfloat16(v.z), h3 = __float2bfloat16(v.w);
    uint2 hp, lp;
    hp.x = pack2(h0, h1); hp.y = pack2(h2, h3);
    lp.x = pack2(__float2bfloat16(v.x - __bfloat162float(h0)),
                 __float2bfloat16(v.y - __bfloat162float(h1)));
    lp.y = pack2(__float2bfloat16(v.z - __bfloat162float(h2)),
                 __float2bfloat16(v.w - __bfloat162float(h3)));
    *(uint2*)(h + i4 * 4) = hp;
    *(uint2*)(l + i4 * 4) = lp;
}

// ======================= fp32 -> fp16 convert (k) ==========================
__global__ __launch_bounds__(256)
void cvt_h_kernel(const float* __restrict__ in, __half* __restrict__ o)
{
    const size_t i4 = (size_t)blockIdx.x * 256 + threadIdx.x;
    float4 v = *(const float4*)(in + i4 * 4);
    uint2 p;
    p.x = pack2h(__float2half(v.x), __float2half(v.y));
    p.y = pack2h(__float2half(v.z), __float2half(v.w));
    *(uint2*)(o + i4 * 4) = p;
}

// ======================= small fp32 GEMM (content bias only) ===============
__global__ __launch_bounds__(256)
void gemm_nt_kernel(const float* __restrict__ A, const float* __restrict__ W,
                    float* __restrict__ out, int M, int N, int K)
{
    __shared__ float As[16][68];
    __shared__ float Ws[16][68];
    const int tid = threadIdx.x;
    const int m0 = blockIdx.y * 64;
    const int lr = tid >> 2, lc = (tid & 3) * 4;
    const int ty = tid >> 4, tx = tid & 15;

    float acc[4][4];
#pragma unroll
    for (int r = 0; r < 4; r++)
#pragma unroll
        for (int c = 0; c < 4; c++) acc[r][c] = 0.f;

    const float* Aptr = A + (size_t)(m0 + lr) * K + lc;
    const int n = lr;
    const float* Wptr = W + (size_t)n * K + lc;
    const bool nok = (n < N);

    for (int k0 = 0; k0 < K; k0 += 16) {
        float4 a = *(const float4*)(Aptr + k0);
        float4 w = make_float4(0.f, 0.f, 0.f, 0.f);
        if (nok) w = *(const float4*)(Wptr + k0);
        __syncthreads();
        As[lc + 0][lr] = a.x; As[lc + 1][lr] = a.y; As[lc + 2][lr] = a.z; As[lc + 3][lr] = a.w;
        Ws[lc + 0][lr] = w.x; Ws[lc + 1][lr] = w.y; Ws[lc + 2][lr] = w.z; Ws[lc + 3][lr] = w.w;
        __syncthreads();
#pragma unroll
        for (int kk = 0; kk < 16; kk++) {
            float4 av = *(const float4*)&As[kk][ty * 4];
            float4 wv = *(const float4*)&Ws[kk][tx * 4];
            acc[0][0] += av.x * wv.x; acc[0][1] += av.x * wv.y; acc[0][2] += av.x * wv.z; acc[0][3] += av.x * wv.w;
            acc[1][0] += av.y * wv.x; acc[1][1] += av.y * wv.y; acc[1][2] += av.y * wv.z; acc[1][3] += av.y * wv.w;
            acc[2][0] += av.z * wv.x; acc[2][1] += av.z * wv.y; acc[2][2] += av.z * wv.z; acc[2][3] += av.z * wv.w;
            acc[3][0] += av.w * wv.x; acc[3][1] += av.w * wv.y; acc[3][2] += av.w * wv.z; acc[3][3] += av.w * wv.w;
        }
    }
#pragma unroll
    for (int r = 0; r < 4; r++) {
        const int m = m0 + ty * 4 + r;
#pragma unroll
        for (int c = 0; c < 4; c++) {
            const int nn = tx * 4 + c;
            if (nn < N) out[(size_t)m * N + nn] = acc[r][c];
        }
    }
}

// ======================= generic HMMA NT GEMM (projections) ================
#define PJ_STAGE 65536
#define PJ_AH 0
#define PJ_AL 16384
#define PJ_BH 32768
#define PJ_BL 49152
#define PJ_NST 16

__global__ __launch_bounds__(256, 1)
void hmma_nt_kernel(const __nv_bfloat16* __restrict__ Ahp, const __nv_bfloat16* __restrict__ Alp,
                    const __nv_bfloat16* __restrict__ Bhp, const __nv_bfloat16* __restrict__ Blp,
                    const float* __restrict__ bias, const float* __restrict__ resid,
                    float* __restrict__ C, int N)
{
    extern __shared__ __align__(1024) char smem[];
    const uint32_t sb = smem_to_u32(smem);

    const int tid = threadIdx.x;
    const int wid = tid >> 5;
    const int lane = tid & 31;
    const int m0 = blockIdx.y * 128;
    const int n0 = blockIdx.x * 128;
    const int warp_m = wid >> 2;
    const int warp_n = wid & 3;

    const __nv_bfloat16* Ah_b = Ahp + (size_t)m0 * DKK;
    const __nv_bfloat16* Al_b = Alp + (size_t)m0 * DKK;
    const __nv_bfloat16* Bh_b = Bhp + (size_t)n0 * DKK;
    const __nv_bfloat16* Bl_b = Blp + (size_t)n0 * DKK;

    float acc[4][4][4];
#pragma unroll
    for (int mt = 0; mt < 4; mt++)
#pragma unroll
        for (int nt = 0; nt < 4; nt++)
#pragma unroll
            for (int e = 0; e < 4; e++) acc[mt][nt][e] = 0.f;

    int cso[4];
    size_t cgi[4];
#pragma unroll
    for (int r = 0; r < 4; r++) {
        const int chunk = tid + 256 * r;
        const int row = chunk >> 3;
        const int cc = chunk & 7;
        cso[r] = row * 128 + ((cc * 16) ^ ((row & 7) << 4));
        cgi[r] = (size_t)row * DKK + cc * 8;
    }

    const int rowA = warp_m * 64 + (lane & 15);
    const int colA = ((lane >> 4) << 4);
    const uint32_t maskA = (rowA & 7) << 4;
    const int rowB = warp_n * 32 + (lane & 7);
    const int colB = ((lane >> 3) & 1) << 4;
    const uint32_t maskB = (rowB & 7) << 4;

    {
        const uint32_t st = sb;
#pragma unroll
        for (int r = 0; r < 4; r++) {
            cp16(st + PJ_AH + cso[r], Ah_b + cgi[r]);
            cp16(st + PJ_AL + cso[r], Al_b + cgi[r]);
            cp16(st + PJ_BH + cso[r], Bh_b + cgi[r]);
            cp16(st + PJ_BL + cso[r], Bl_b + cgi[r]);
        }
        CP_COMMIT();
    }

    for (int s = 0; s < PJ_NST; s++) {
        if (s + 1 < PJ_NST) {
            const uint32_t st = sb + ((s + 1) & 1) * PJ_STAGE;
            const size_t koff = (size_t)(s + 1) * 64;
#pragma unroll
            for (int r = 0; r < 4; r++) {
                cp16(st + PJ_AH + cso[r], Ah_b + cgi[r] + koff);
                cp16(st + PJ_AL + cso[r], Al_b + cgi[r] + koff);
                cp16(st + PJ_BH + cso[r], Bh_b + cgi[r] + koff);
                cp16(st + PJ_BL + cso[r], Bl_b + cgi[r] + koff);
            }
            CP_COMMIT();
            CP_WAIT1();
        } else {
            CP_WAIT0();
        }
        __syncthreads();

        const uint32_t st = sb + (s & 1) * PJ_STAGE;
#pragma unroll
        for (int ks = 0; ks < 4; ks++) {
            const int k0b = ks * 32;
            uint32_t Ahf[4][4], Alf[4][4], Bhf[4][2], Blf[4][2];
#pragma unroll
            for (int mt = 0; mt < 4; mt++)
                ldsm_x4(Ahf[mt], st + PJ_AH + (uint32_t)((rowA + mt * 16) * 128) + (uint32_t)((k0b + colA) ^ maskA));
#pragma unroll
            for (int nt = 0; nt < 4; nt++) {
                ldsm_x2(Bhf[nt], st + PJ_BH + (uint32_t)((rowB + nt * 8) * 128) + (uint32_t)((k0b + colB) ^ maskB));
                ldsm_x2(Blf[nt], st + PJ_BL + (uint32_t)((rowB + nt * 8) * 128) + (uint32_t)((k0b + colB) ^ maskB));
            }
#pragma unroll
            for (int mt = 0; mt < 4; mt++)
#pragma unroll
                for (int nt = 0; nt < 4; nt++)
                    mma_bf16(acc[mt][nt], Ahf[mt], Bhf[nt]);
#pragma unroll
            for (int mt = 0; mt < 4; mt++)
                ldsm_x4(Alf[mt], st + PJ_AL + (uint32_t)((rowA + mt * 16) * 128) + (uint32_t)((k0b + colA) ^ maskA));
#pragma unroll
            for (int mt = 0; mt < 4; mt++)
#pragma unroll
                for (int nt = 0; nt < 4; nt++)
                    mma_bf16(acc[mt][nt], Ahf[mt], Blf[nt]);
#pragma unroll
            for (int mt = 0; mt < 4; mt++)
#pragma unroll
                for (int nt = 0; nt < 4; nt++)
                    mma_bf16(acc[mt][nt], Alf[mt], Bhf[nt]);
        }
        __syncthreads();
    }

    const int r0 = lane >> 2;
    const int c0 = (lane & 3) * 2;
#pragma unroll
    for (int mt = 0; mt < 4; mt++) {
        const int mrow = m0 + warp_m * 64 + mt * 16 + r0;
#pragma unroll
        for (int nt = 0; nt < 4; nt++) {
            const int ncol = n0 + warp_n * 32 + nt * 8 + c0;
#pragma unroll
            for (int half = 0; half < 2; half++) {
                const int m = mrow + half * 8;
                float2 v = half ? make_float2(acc[mt][nt][2], acc[mt][nt][3])
                                : make_float2(acc[mt][nt][0], acc[mt][nt][1]);
                if (bias)  { v.x += bias[ncol]; v.y += bias[ncol + 1]; }
                if (resid) {
                    float2 rr = *(const float2*)(resid + (size_t)m * N + ncol);
                    v.x += rr.x; v.y += rr.y;
                }
                *(float2*)(C + (size_t)m * N + ncol) = v;
            }
        }
    }
}

// ======================= prep q (fold mixing*scale, fp16 hi/lo) ============
__global__ __launch_bounds__(256)
void prep_q_kernel(const float* __restrict__ q, const float* __restrict__ mixing,
                   __half* __restrict__ qh, __half* __restrict__ ql)
{
    const int bh = blockIdx.y;
    const int b = bh >> 4, h = bh & 15;
    const size_t i4 = (size_t)blockIdx.x * 256 + threadIdx.x;
    const int s = (int)(i4 >> 8);
    const int c4 = (int)(i4 & 255);
    float4 v = *(const float4*)(q + ((size_t)b * SS + s) * DKK + c4 * 4);
    float4 m = *(const float4*)(mixing + (size_t)h * DKK + c4 * 4);
    v.x *= m.x * SCALE; v.y *= m.y * SCALE; v.z *= m.z * SCALE; v.w *= m.w * SCALE;
    __half h0 = __float2half(v.x), h1 = __float2half(v.y);
    __half h2 = __float2half(v.z), h3 = __float2half(v.w);
    uint2 hp, lp;
    hp.x = pack2h(h0, h1); hp.y = pack2h(h2, h3);
    lp.x = pack2h(__float2half(v.x - __half2float(h0)),
                  __float2half(v.y - __half2float(h1)));
    lp.y = pack2h(__float2half(v.z - __half2float(h2)),
                  __float2half(v.w - __half2float(h3)));
    const size_t o = ((size_t)bh * SS + s) * DKK + c4 * 4;
    *(uint2*)(qh + o) = hp;
    *(uint2*)(ql + o) = lp;
}

// ======================= prep V^T per head (bf16 hi/lo) ====================
__global__ __launch_bounds__(256)
void prep_vt_kernel(const float* __restrict__ v,
                    __nv_bfloat16* __restrict__ vth, __nv_bfloat16* __restrict__ vtl)
{
    const int tid = threadIdx.x;
    const int bh = blockIdx.z;
    const int b = bh >> 4, h = bh & 15;
    const int j = blockIdx.x * 64 + (tid & 63);
    const int vvg = blockIdx.y * 4 + (tid >> 6);
    float4 v4 = *(const float4*)(v + ((size_t)b * SS + j) * DVV + h * HEADV + vvg * 4);
#pragma unroll
    for (int e = 0; e < 4; e++) {
        float val = (&v4.x)[e];
        __nv_bfloat16 hh = __float2bfloat16(val);
        __nv_bfloat16 ll = __float2bfloat16(val - __bfloat162float(hh));
        const size_t o = ((size_t)bh * HEADV + vvg * 4 + e) * SS + j;
        vth[o] = hh; vtl[o] = ll;
    }
}

__global__ __launch_bounds__(256)
void cbt_kernel(const float* __restrict__ cb, float* __restrict__ cbt)
{
    const int bh = blockIdx.y;
    const int b = bh >> 4, h = bh & 15;
    const int j = blockIdx.x * 256 + threadIdx.x;
    cbt[(size_t)bh * SS + j] = cb[((size_t)b * SS + j) * HH + h] * SCALE;
}

// ======================= HMMA scores GEMM (128x256, fp16 2-pass) ===========
// A = q*mix*scale (fp16 hi/lo), B = k (fp16 single). 2 passes: Ah*B + Al*B.
#define SC_AH 0
#define SC_AL 16384
#define SC_B  32768
#define SC_STAGE 65536          // 64 KB per stage
#define SC_NST 16

__global__ __launch_bounds__(256, 1)
void scores_kernel(const __half* __restrict__ qh, const __half* __restrict__ ql,
                   const __half* __restrict__ kf, float* __restrict__ scores)
{
    extern __shared__ __align__(1024) char smem[];
    const uint32_t sb = smem_to_u32(smem);

    const int tid = threadIdx.x;
    const int wid = tid >> 5;
    const int lane = tid & 31;
    const int bh = blockIdx.z;
    const int b = bh >> 4;
    const int i0 = blockIdx.y * 128;
    const int j0 = blockIdx.x * 256;
    const int warp_m = wid >> 2;     // 0..1 (64 rows)
    const int warp_n = wid & 3;      // 0..3 (64 cols)

    const __half* qh_b = qh + ((size_t)bh * SS + i0) * DKK;
    const __half* ql_b = ql + ((size_t)bh * SS + i0) * DKK;
    const __half* kf_b = kf + ((size_t)b * SS + j0) * DKK;

    float acc[4][8][4];
#pragma unroll
    for (int mt = 0; mt < 4; mt++)
#pragma unroll
        for (int nn = 0; nn < 8; nn++)
#pragma unroll
            for (int e = 0; e < 4; e++) acc[mt][nn][e] = 0.f;

    int csoA[4];  size_t cgiA[4];
#pragma unroll
    for (int r = 0; r < 4; r++) {
        const int chunk = tid + 256 * r;
        const int row = chunk >> 3, cc = chunk & 7;
        csoA[r] = row * 128 + ((cc * 16) ^ ((row & 7) << 4));
        cgiA[r] = (size_t)row * DKK + cc * 8;
    }
    int csoB[8];  size_t cgiB[8];
#pragma unroll
    for (int r = 0; r < 8; r++) {
        const int chunk = tid + 256 * r;
        const int row = chunk >> 3, cc = chunk & 7;
        csoB[r] = row * 128 + ((cc * 16) ^ ((row & 7) << 4));
        cgiB[r] = (size_t)row * DKK + cc * 8;
    }

    {
        const uint32_t st = sb;
#pragma unroll
        for (int r = 0; r < 4; r++) {
            cp16(st + SC_AH + csoA[r], qh_b + cgiA[r]);
            cp16(st + SC_AL + csoA[r], ql_b + cgiA[r]);
        }
#pragma unroll
        for (int r = 0; r < 8; r++)
            cp16(st + SC_B + csoB[r], kf_b + cgiB[r]);
        CP_COMMIT();
    }

    for (int s = 0; s < SC_NST; s++) {
        if (s + 1 < SC_NST) {
            const uint32_t st = sb + ((s + 1) & 1) * SC_STAGE;
            const size_t koff = (size_t)(s + 1) * 64;
#pragma unroll
            for (int r = 0; r < 4; r++) {
                cp16(st + SC_AH + csoA[r], qh_b + cgiA[r] + koff);
                cp16(st + SC_AL + csoA[r], ql_b + cgiA[r] + koff);
            }
#pragma unroll
            for (int r = 0; r < 8; r++)
                cp16(st + SC_B + csoB[r], kf_b + cgiB[r] + koff);
            CP_COMMIT();
            CP_WAIT1();
        } else {
            CP_WAIT0();
        }
        __syncthreads();

        const uint32_t st = sb + (s & 1) * SC_STAGE;
#pragma unroll
        for (int ks = 0; ks < 4; ks++) {
            const int k0b = ks * 32;
            uint32_t Ahf[4][4], Alf[4][4];
#pragma unroll
            for (int mt = 0; mt < 4; mt++) {
                const int rowA = warp_m * 64 + mt * 16 + (lane & 15);
                const uint32_t cA = (uint32_t)((k0b + ((lane >> 4) << 4)) ^ ((rowA & 7) << 4));
                ldsm_x4(Ahf[mt], st + SC_AH + (uint32_t)(rowA * 128) + cA);
                ldsm_x4(Alf[mt], st + SC_AL + (uint32_t)(rowA * 128) + cA);
            }
#pragma unroll
            for (int ng = 0; ng < 4; ng++) {
                const int rowB = warp_n * 64 + ng * 16 + (lane & 7) + ((lane & 16) >> 1);
                const uint32_t cB = (uint32_t)((k0b + (((lane >> 3) & 1) << 4)) ^ ((rowB & 7) << 4));
                uint32_t B4[4];
                ldsm_x4(B4, st + SC_B + (uint32_t)(rowB * 128) + cB);
#pragma unroll
                for (int mt = 0; mt < 4; mt++) {
                    mma_fp16(acc[mt][ng * 2 + 0], Ahf[mt], B4 + 0);
                    mma_fp16(acc[mt][ng * 2 + 1], Ahf[mt], B4 + 2);
                    mma_fp16(acc[mt][ng * 2 + 0], Alf[mt], B4 + 0);
                    mma_fp16(acc[mt][ng * 2 + 1], Alf[mt], B4 + 2);
                }
            }
        }
        __syncthreads();
    }

    const int r0 = lane >> 2;
    const int c0 = (lane & 3) * 2;
#pragma unroll
    for (int mt = 0; mt < 4; mt++) {
        float* base = scores + ((size_t)bh * SS + i0 + warp_m * 64 + mt * 16 + r0) * SS
                             + j0 + warp_n * 64 + c0;
#pragma unroll
        for (int nn = 0; nn < 8; nn++) {
            *(float2*)(base + nn * 8) = make_float2(acc[mt][nn][0], acc[mt][nn][1]);
            *(float2*)(base + 8 * SS + nn * 8) = make_float2(acc[mt][nn][2], acc[mt][nn][3]);
        }
    }
}

// ======================= fused softmax + PV (flash over scores) ============
#define FP_PH 0
#define FP_PL 32768
#define FP_VH 65536
#define FP_VL 81920
#define FP_M  98304
#define FP_SC 98816
#define FP_L  99328
#define FP_SMEM 99840

__global__ __launch_bounds__(256, 1)
void fused_pv_kernel(const float* __restrict__ scores, const float* __restrict__ cbt,
                     const __nv_bfloat16* __restrict__ vth, const __nv_bfloat16* __restrict__ vtl,
                     float* __restrict__ ctx)
{
    extern __shared__ __align__(1024) char sm[];
    const uint32_t sb = smem_to_u32(sm);
    float* sm_m  = (float*)(sm + FP_M);
    float* sm_sc = (float*)(sm + FP_SC);
    float* sm_l  = (float*)(sm + FP_L);

    const int tid = threadIdx.x;
    const int wid = tid >> 5;
    const int lane = tid & 31;
    const int bh = blockIdx.y;
    const int b = bh >> 4, h = bh & 15;
    const int i0 = blockIdx.x * 128;

    if (tid < 128) { sm_m[tid] = -INFINITY; sm_l[tid] = 0.f; }

    float acc[8][4];
#pragma unroll
    for (int nn = 0; nn < 8; nn++)
#pragma unroll
        for (int e = 0; e < 4; e++) acc[nn][e] = 0.f;

    const int srow = tid >> 1;
    const int sch = tid & 1;
    const float* sptr = scores + ((size_t)bh * SS + i0 + srow) * SS + sch * 64;
    const float* cptr = cbt + (size_t)bh * SS + sch * 64;

    const int m0 = wid * 16;
    const int r0 = m0 + (lane >> 2);
    const int r1 = r0 + 8;

    __syncthreads();

    for (int j0 = 0; j0 < SS; j0 += 128) {
#pragma unroll
        for (int r = 0; r < 4; r++) {
            const int id = tid + 256 * r;
            const int row = id >> 4, cc = id & 15;
            const uint32_t so = (uint32_t)(row * 256 + ((cc * 16) ^ ((row & 7) << 4)));
            const size_t gi = ((size_t)bh * HEADV + row) * SS + j0 + cc * 8;
            cp16(sb + FP_VH + so, vth + gi);
            cp16(sb + FP_VL + so, vtl + gi);
        }
        CP_COMMIT();

        float vals[64];
        float tmax = -INFINITY;
#pragma unroll
        for (int c4 = 0; c4 < 16; c4++) {
            float4 s4 = *(const float4*)(sptr + j0 + c4 * 4);
            float4 cb4 = *(const float4*)(cptr + j0 + c4 * 4);
            s4.x += cb4.x; s4.y += cb4.y; s4.z += cb4.z; s4.w += cb4.w;
            vals[c4 * 4 + 0] = s4.x; vals[c4 * 4 + 1] = s4.y;
            vals[c4 * 4 + 2] = s4.z; vals[c4 * 4 + 3] = s4.w;
            tmax = fmaxf(tmax, fmaxf(fmaxf(s4.x, s4.y), fmaxf(s4.z, s4.w)));
        }
        tmax = fmaxf(tmax, __shfl_xor_sync(0xffffffffu, tmax, 1));
        const float mold = sm_m[srow];
        const float mnew = fmaxf(mold, tmax);
        const float scl = __expf(mold - mnew);
        float rsum = 0.f;
#pragma unroll
        for (int c = 0; c < 64; c++) { vals[c] = __expf(vals[c] - mnew); rsum += vals[c]; }
        rsum += __shfl_xor_sync(0xffffffffu, rsum, 1);
        if (sch == 0) {
            sm_l[srow] = sm_l[srow] * scl + rsum;
            sm_m[srow] = mnew;
            sm_sc[srow] = scl;
        }
#pragma unroll
        for (int c4 = 0; c4 < 16; c4++) {
            float p0 = vals[c4 * 4 + 0], p1 = vals[c4 * 4 + 1];
            float p2 = vals[c4 * 4 + 2], p3 = vals[c4 * 4 + 3];
            __nv_bfloat16 h0 = __float2bfloat16(p0), h1 = __float2bfloat16(p1);
            __nv_bfloat16 h2 = __float2bfloat16(p2), h3 = __float2bfloat16(p3);
            uint2 hp, lp;
            hp.x = pack2(h0, h1); hp.y = pack2(h2, h3);
            lp.x = pack2(__float2bfloat16(p0 - __bfloat162float(h0)),
                         __float2bfloat16(p1 - __bfloat162float(h1)));
            lp.y = pack2(__float2bfloat16(p2 - __bfloat162float(h2)),
                         __float2bfloat16(p3 - __bfloat162float(h3)));
            const uint32_t colbyte = (uint32_t)(sch * 128 + c4 * 8);
            const uint32_t off = (uint32_t)(srow * 256) + (colbyte ^ ((srow & 7) << 4));
            *(uint2*)(sm + FP_PH + off) = hp;
            *(uint2*)(sm + FP_PL + off) = lp;
        }
        CP_WAIT0();
        __syncthreads();

        const float s0 = sm_sc[r0];
        const float s1 = sm_sc[r1];
#pragma unroll
        for (int nn = 0; nn < 8; nn++) {
            acc[nn][0] *= s0; acc[nn][1] *= s0;
            acc[nn][2] *= s1; acc[nn][3] *= s1;
        }
#pragma unroll
        for (int ks = 0; ks < 8; ks++) {
            const int k0b = ks * 32;
            uint32_t Ah4[4], Al4[4];
            const int rowa = m0 + (lane & 15);
            const uint32_t cA = (uint32_t)((k0b + ((lane >> 4) << 4)) ^ ((rowa & 7) << 4));
            ldsm_x4(Ah4, sb + FP_PH + (uint32_t)(rowa * 256) + cA);
            ldsm_x4(Al4, sb + FP_PL + (uint32_t)(rowa * 256) + cA);
#pragma unroll
            for (int ng = 0; ng < 4; ng++) {
                const int rowb = ng * 16 + (lane & 7) + ((lane & 16) >> 1);
                const uint32_t cB = (uint32_t)((k0b + (((lane >> 3) & 1) << 4)) ^ ((rowb & 7) << 4));
                uint32_t Bh4[4], Bl4[4];
                ldsm_x4(Bh4, sb + FP_VH + (uint32_t)(rowb * 256) + cB);
                mma_bf16(acc[ng * 2 + 0], Ah4, Bh4 + 0);
                mma_bf16(acc[ng * 2 + 1], Ah4, Bh4 + 2);
                mma_bf16(acc[ng * 2 + 0], Al4, Bh4 + 0);
                mma_bf16(acc[ng * 2 + 1], Al4, Bh4 + 2);
                ldsm_x4(Bl4, sb + FP_VL + (uint32_t)(rowb * 256) + cB);
                mma_bf16(acc[ng * 2 + 0], Ah4, Bl4 + 0);
                mma_bf16(acc[ng * 2 + 1], Ah4, Bl4 + 2);
            }
        }
        __syncthreads();
    }

    const float inv0 = 1.f / sm_l[r0];
    const float inv1 = 1.f / sm_l[r1];
    const int c0 = (lane & 3) * 2;
#pragma unroll
    for (int nn = 0; nn < 8; nn++) {
        const int col = h * HEADV + nn * 8 + c0;
        *(float2*)(ctx + ((size_t)b * SS + i0 + r0) * DVV + col) =
            make_float2(acc[nn][0] * inv0, acc[nn][1] * inv0);
        *(float2*)(ctx + ((size_t)b * SS + i0 + r1) * DVV + col) =
            make_float2(acc[nn][2] * inv1, acc[nn][3] * inv1);
    }
}

// ======================= LayerNorm =========================================
__global__ __launch_bounds__(256)
void ln_kernel(const float* __restrict__ res, const float* __restrict__ gamma,
               const float* __restrict__ beta, float* __restrict__ out)
{
    const int row = blockIdx.x;
    const int c = threadIdx.x * 4;
    const float4 v = *(const float4*)(res + (size_t)row * DOUT + c);
    float s  = v.x + v.y + v.z + v.w;
    float s2 = v.x * v.x + v.y * v.y + v.z * v.z + v.w * v.w;
#pragma unroll
    for (int o = 16; o >= 1; o >>= 1) {
        s  += __shfl_xor_sync(0xffffffffu, s,  o);
        s2 += __shfl_xor_sync(0xffffffffu, s2, o);
    }
    __shared__ float sh[8], sh2[8];
    __shared__ float mu_s, inv_s;
    const int w = threadIdx.x >> 5;
    if ((threadIdx.x & 31) == 0) { sh[w] = s; sh2[w] = s2; }
    __syncthreads();
    if (threadIdx.x == 0) {
        float S = 0.f, S2 = 0.f;
#pragma unroll
        for (int i = 0; i < 8; i++) { S += sh[i]; S2 += sh2[i]; }
        const float mu = S * (1.f / DOUT);
        const float var = S2 * (1.f / DOUT) - mu * mu;
        mu_s = mu; inv_s = rsqrtf(var + LN_EPS);
    }
    __syncthreads();
    const float mu = mu_s, inv = inv_s;
    const float4 g  = *(const float4*)(gamma + c);
    const float4 bt = *(const float4*)(beta + c);
    float4 o;
    o.x = (v.x - mu) * inv * g.x + bt.x;
    o.y = (v.y - mu) * inv * g.y + bt.y;
    o.z = (v.z - mu) * inv * g.z + bt.z;
    o.w = (v.w - mu) * inv * g.w + bt.w;
    *(float4*)(out + (size_t)row * DOUT + c) = o;
}

// ===========================================================================
extern "C" void kernel_launch(void* const* d_in, const int* in_sizes, int n_in,
                              void* d_out, int out_size)
{
    const float* x      = (const float*)d_in[0];
    const float* Wq     = (const float*)d_in[1];
    const float* Wk     = (const float*)d_in[2];
    const float* Wcb    = (const float*)d_in[3];
    const float* Wv     = (const float*)d_in[4];
    const float* bv     = (const float*)d_in[5];
    const float* mixing = (const float*)d_in[6];
    const float* Wd     = (const float*)d_in[7];
    const float* bd     = (const float*)d_in[8];
    const float* gamma  = (const float*)d_in[9];
    const float* beta   = (const float*)d_in[10];
    float* out = (float*)d_out;

    float *q, *k, *v, *ctx, *res, *cb, *cbt, *scores;
    __half *qh, *ql, *kf;
    __nv_bfloat16 *xh, *xl, *wh, *wl, *vth, *vtl, *cxh, *cxl;
    cudaGetSymbolAddress((void**)&q,      g_q);
    cudaGetSymbolAddress((void**)&k,      g_k);
    cudaGetSymbolAddress((void**)&v,      g_v);
    cudaGetSymbolAddress((void**)&ctx,    g_ctx);
    cudaGetSymbolAddress((void**)&res,    g_res);
    cudaGetSymbolAddress((void**)&cb,     g_cb);
    cudaGetSymbolAddress((void**)&cbt,    g_cbt);
    cudaGetSymbolAddress((void**)&scores, g_scores);
    cudaGetSymbolAddress((void**)&qh,     g_qh);
    cudaGetSymbolAddress((void**)&ql,     g_ql);
    cudaGetSymbolAddress((void**)&kf,     g_kf);
    cudaGetSymbolAddress((void**)&xh,     g_xh);
    cudaGetSymbolAddress((void**)&xl,     g_xl);
    cudaGetSymbolAddress((void**)&wh,     g_wh);
    cudaGetSymbolAddress((void**)&wl,     g_wl);
    cudaGetSymbolAddress((void**)&vth,    g_vth);
    cudaGetSymbolAddress((void**)&vtl,    g_vtl);
    cudaGetSymbolAddress((void**)&cxh,    g_cxh);
    cudaGetSymbolAddress((void**)&cxl,    g_cxl);

    cudaFuncSetAttribute(scores_kernel,   cudaFuncAttributeMaxDynamicSharedMemorySize, 2 * SC_STAGE);
    cudaFuncSetAttribute(hmma_nt_kernel,  cudaFuncAttributeMaxDynamicSharedMemorySize, 2 * PJ_STAGE);
    cudaFuncSetAttribute(fused_pv_kernel, cudaFuncAttributeMaxDynamicSharedMemorySize, FP_SMEM);

    const size_t WSZ = 1024 * 1024;

    // splits
    split_kernel<<<MROWS * DIN / 1024, 256>>>(x, xh, xl);
    split_kernel<<<WSZ / 1024, 256>>>(Wq, wh + 0 * WSZ, wl + 0 * WSZ);
    split_kernel<<<WSZ / 1024, 256>>>(Wk, wh + 1 * WSZ, wl + 1 * WSZ);
    split_kernel<<<WSZ / 1024, 256>>>(Wv, wh + 2 * WSZ, wl + 2 * WSZ);
    split_kernel<<<WSZ / 1024, 256>>>(Wd, wh + 3 * WSZ, wl + 3 * WSZ);

    // projections (HMMA)
    dim3 gProj(DKK / 128, MROWS / 128);    // (8, 32)
    hmma_nt_kernel<<<gProj, 256, 2 * PJ_STAGE>>>(xh, xl, wh + 0 * WSZ, wl + 0 * WSZ, nullptr, nullptr, q, DKK);
    hmma_nt_kernel<<<gProj, 256, 2 * PJ_STAGE>>>(xh, xl, wh + 1 * WSZ, wl + 1 * WSZ, nullptr, nullptr, k, DKK);
    hmma_nt_kernel<<<gProj, 256, 2 * PJ_STAGE>>>(xh, xl, wh + 2 * WSZ, wl + 2 * WSZ, bv, nullptr, v, DVV);
    gemm_nt_kernel<<<dim3(1, MROWS / 64), 256>>>(x, Wcb, cb, MROWS, HH, DIN);

    // attention preps
    cvt_h_kernel<<<MROWS * DKK / 1024, 256>>>(k, kf);
    prep_q_kernel<<<dim3(SS * DKK / 4 / 256, BH), 256>>>(q, mixing, qh, ql);
    prep_vt_kernel<<<dim3(SS / 64, HEADV / 16, BH), 256>>>(v, vth, vtl);
    cbt_kernel<<<dim3(SS / 256, BH), 256>>>(cb, cbt);

    // attention
    scores_kernel<<<dim3(SS / 256, SS / 128, BH), 256, 2 * SC_STAGE>>>(qh, ql, kf, scores);
    fused_pv_kernel<<<dim3(SS / 128, BH), 256, FP_SMEM>>>(scores, cbt, vth, vtl, ctx);

    // output projection + residual + LN
    split_kernel<<<MROWS * DVV / 1024, 256>>>(ctx, cxh, cxl);
    hmma_nt_kernel<<<gProj, 256, 2 * PJ_STAGE>>>(cxh, cxl, wh + 3 * WSZ, wl + 3 * WSZ, bd, x, res, DOUT);
    ln_kernel<<<MROWS, 256>>>(res, gamma, beta, out);
}

// round 8
// speedup vs baseline: 1.9900x; 1.9900x over previous
#include <cuda_runtime.h>
#include <cuda_bf16.h>
#include <math.h>
#include <stdint.h>

// Problem constants
#define BB 2
#define SS 2048
#define DIN 1024
#define HH 16
#define DKK 1024
#define DVV 1024
#define DOUT 1024
#define MROWS (BB*SS)          // 4096
#define BH (BB*HH)             // 32
#define HEADV 64
#define SCALE 0.125f
#define LN_EPS 1e-5f

// Scratch
__device__ float g_q  [(size_t)MROWS * DKK];
__device__ float g_k  [(size_t)MROWS * DKK];
__device__ float g_v  [(size_t)MROWS * DVV];
__device__ float g_ctx[(size_t)MROWS * DVV];
__device__ float g_res[(size_t)MROWS * DOUT];
__device__ float g_cb [(size_t)MROWS * HH];
__device__ float g_cbt[(size_t)BH * SS];
__device__ float g_scores[(size_t)BH * SS * SS];            // 536 MB
__device__ __nv_bfloat16 g_qm[(size_t)BH * SS * DKK];       // q*mix*scale, single bf16
__device__ __nv_bfloat16 g_kb[(size_t)MROWS * DKK];         // k single bf16
__device__ __nv_bfloat16 g_xh[(size_t)MROWS * DIN];
__device__ __nv_bfloat16 g_xl[(size_t)MROWS * DIN];
__device__ __nv_bfloat16 g_wh[(size_t)4 * 1024 * 1024];
__device__ __nv_bfloat16 g_wl[(size_t)4 * 1024 * 1024];
__device__ __nv_bfloat16 g_vth[(size_t)BH * HEADV * SS];
__device__ __nv_bfloat16 g_vtl[(size_t)BH * HEADV * SS];
__device__ __nv_bfloat16 g_cxh[(size_t)MROWS * DVV];
__device__ __nv_bfloat16 g_cxl[(size_t)MROWS * DVV];

// ======================= helpers ===========================================
__device__ __forceinline__ uint32_t smem_to_u32(const void* p) {
    uint32_t a;
    asm("{ .reg .u64 t; cvta.to.shared.u64 t, %1; cvt.u32.u64 %0, t; }" : "=r"(a) : "l"(p));
    return a;
}
__device__ __forceinline__ void cp16(uint32_t s, const void* g) {
    asm volatile("cp.async.cg.shared.global [%0], [%1], 16;" :: "r"(s), "l"(g));
}
#define CP_COMMIT() asm volatile("cp.async.commit_group;" ::: "memory")
#define CP_WAIT1()  asm volatile("cp.async.wait_group 1;" ::: "memory")
#define CP_WAIT0()  asm volatile("cp.async.wait_group 0;" ::: "memory")

__device__ __forceinline__ void ldsm_x4(uint32_t* r, uint32_t addr) {
    asm volatile("ldmatrix.sync.aligned.m8n8.x4.shared.b16 {%0,%1,%2,%3}, [%4];"
        : "=r"(r[0]), "=r"(r[1]), "=r"(r[2]), "=r"(r[3]) : "r"(addr));
}
__device__ __forceinline__ void ldsm_x2(uint32_t* r, uint32_t addr) {
    asm volatile("ldmatrix.sync.aligned.m8n8.x2.shared.b16 {%0,%1}, [%2];"
        : "=r"(r[0]), "=r"(r[1]) : "r"(addr));
}
__device__ __forceinline__ void mma_bf16(float* c, const uint32_t* a, const uint32_t* b) {
    asm volatile("mma.sync.aligned.m16n8k16.row.col.f32.bf16.bf16.f32 "
        "{%0,%1,%2,%3}, {%4,%5,%6,%7}, {%8,%9}, {%0,%1,%2,%3};"
        : "+f"(c[0]), "+f"(c[1]), "+f"(c[2]), "+f"(c[3])
        : "r"(a[0]), "r"(a[1]), "r"(a[2]), "r"(a[3]), "r"(b[0]), "r"(b[1]));
}
__device__ __forceinline__ uint32_t pack2(__nv_bfloat16 a, __nv_bfloat16 b) {
    return (uint32_t)__bfloat16_as_ushort(a) | ((uint32_t)__bfloat16_as_ushort(b) << 16);
}

// ======================= generic fp32 -> bf16 hi/lo split ==================
__global__ __launch_bounds__(256)
void split_kernel(const float* __restrict__ in,
                  __nv_bfloat16* __restrict__ h, __nv_bfloat16* __restrict__ l)
{
    const size_t i4 = (size_t)blockIdx.x * 256 + threadIdx.x;
    float4 v = *(const float4*)(in + i4 * 4);
    __nv_bfloat16 h0 = __float2bfloat16(v.x), h1 = __float2bfloat16(v.y);
    __nv_bfloat16 h2 = __float2bfloat16(v.z), h3 = __float2bfloat16(v.w);
    uint2 hp, lp;
    hp.x = pack2(h0, h1); hp.y = pack2(h2, h3);
    lp.x = pack2(__float2bfloat16(v.x - __bfloat162float(h0)),
                 __float2bfloat16(v.y - __bfloat162float(h1)));
    lp.y = pack2(__float2bfloat16(v.z - __bfloat162float(h2)),
                 __float2bfloat16(v.w - __bfloat162float(h3)));
    *(uint2*)(h + i4 * 4) = hp;
    *(uint2*)(l + i4 * 4) = lp;
}

// ======================= fp32 -> bf16 convert (k) ==========================
__global__ __launch_bounds__(256)
void cvt_bf_kernel(const float* __restrict__ in, __nv_bfloat16* __restrict__ o)
{
    const size_t i4 = (size_t)blockIdx.x * 256 + threadIdx.x;
    float4 v = *(const float4*)(in + i4 * 4);
    uint2 p;
    p.x = pack2(__float2bfloat16(v.x), __float2bfloat16(v.y));
    p.y = pack2(__float2bfloat16(v.z), __float2bfloat16(v.w));
    *(uint2*)(o + i4 * 4) = p;
}

// ======================= small fp32 GEMM (content bias only) ===============
__global__ __launch_bounds__(256)
void gemm_nt_kernel(const float* __restrict__ A, const float* __restrict__ W,
                    float* __restrict__ out, int M, int N, int K)
{
    __shared__ float As[16][68];
    __shared__ float Ws[16][68];
    const int tid = threadIdx.x;
    const int m0 = blockIdx.y * 64;
    const int lr = tid >> 2, lc = (tid & 3) * 4;
    const int ty = tid >> 4, tx = tid & 15;

    float acc[4][4];
#pragma unroll
    for (int r = 0; r < 4; r++)
#pragma unroll
        for (int c = 0; c < 4; c++) acc[r][c] = 0.f;

    const float* Aptr = A + (size_t)(m0 + lr) * K + lc;
    const int n = lr;
    const float* Wptr = W + (size_t)n * K + lc;
    const bool nok = (n < N);

    for (int k0 = 0; k0 < K; k0 += 16) {
        float4 a = *(const float4*)(Aptr + k0);
        float4 w = make_float4(0.f, 0.f, 0.f, 0.f);
        if (nok) w = *(const float4*)(Wptr + k0);
        __syncthreads();
        As[lc + 0][lr] = a.x; As[lc + 1][lr] = a.y; As[lc + 2][lr] = a.z; As[lc + 3][lr] = a.w;
        Ws[lc + 0][lr] = w.x; Ws[lc + 1][lr] = w.y; Ws[lc + 2][lr] = w.z; Ws[lc + 3][lr] = w.w;
        __syncthreads();
#pragma unroll
        for (int kk = 0; kk < 16; kk++) {
            float4 av = *(const float4*)&As[kk][ty * 4];
            float4 wv = *(const float4*)&Ws[kk][tx * 4];
            acc[0][0] += av.x * wv.x; acc[0][1] += av.x * wv.y; acc[0][2] += av.x * wv.z; acc[0][3] += av.x * wv.w;
            acc[1][0] += av.y * wv.x; acc[1][1] += av.y * wv.y; acc[1][2] += av.y * wv.z; acc[1][3] += av.y * wv.w;
            acc[2][0] += av.z * wv.x; acc[2][1] += av.z * wv.y; acc[2][2] += av.z * wv.z; acc[2][3] += av.z * wv.w;
            acc[3][0] += av.w * wv.x; acc[3][1] += av.w * wv.y; acc[3][2] += av.w * wv.z; acc[3][3] += av.w * wv.w;
        }
    }
#pragma unroll
    for (int r = 0; r < 4; r++) {
        const int m = m0 + ty * 4 + r;
#pragma unroll
        for (int c = 0; c < 4; c++) {
            const int nn = tx * 4 + c;
            if (nn < N) out[(size_t)m * N + nn] = acc[r][c];
        }
    }
}

// ======================= generic HMMA NT GEMM (projections) ================
#define PJ_STAGE 65536
#define PJ_AH 0
#define PJ_AL 16384
#define PJ_BH 32768
#define PJ_BL 49152
#define PJ_NST 16

__global__ __launch_bounds__(256, 1)
void hmma_nt_kernel(const __nv_bfloat16* __restrict__ Ahp, const __nv_bfloat16* __restrict__ Alp,
                    const __nv_bfloat16* __restrict__ Bhp, const __nv_bfloat16* __restrict__ Blp,
                    const float* __restrict__ bias, const float* __restrict__ resid,
                    float* __restrict__ C, int N)
{
    extern __shared__ __align__(1024) char smem[];
    const uint32_t sb = smem_to_u32(smem);

    const int tid = threadIdx.x;
    const int wid = tid >> 5;
    const int lane = tid & 31;
    const int m0 = blockIdx.y * 128;
    const int n0 = blockIdx.x * 128;
    const int warp_m = wid >> 2;
    const int warp_n = wid & 3;

    const __nv_bfloat16* Ah_b = Ahp + (size_t)m0 * DKK;
    const __nv_bfloat16* Al_b = Alp + (size_t)m0 * DKK;
    const __nv_bfloat16* Bh_b = Bhp + (size_t)n0 * DKK;
    const __nv_bfloat16* Bl_b = Blp + (size_t)n0 * DKK;

    float acc[4][4][4];
#pragma unroll
    for (int mt = 0; mt < 4; mt++)
#pragma unroll
        for (int nt = 0; nt < 4; nt++)
#pragma unroll
            for (int e = 0; e < 4; e++) acc[mt][nt][e] = 0.f;

    int cso[4];
    size_t cgi[4];
#pragma unroll
    for (int r = 0; r < 4; r++) {
        const int chunk = tid + 256 * r;
        const int row = chunk >> 3;
        const int cc = chunk & 7;
        cso[r] = row * 128 + ((cc * 16) ^ ((row & 7) << 4));
        cgi[r] = (size_t)row * DKK + cc * 8;
    }

    const int rowA = warp_m * 64 + (lane & 15);
    const int colA = ((lane >> 4) << 4);
    const uint32_t maskA = (rowA & 7) << 4;
    const int rowB = warp_n * 32 + (lane & 7);
    const int colB = ((lane >> 3) & 1) << 4;
    const uint32_t maskB = (rowB & 7) << 4;

    {
        const uint32_t st = sb;
#pragma unroll
        for (int r = 0; r < 4; r++) {
            cp16(st + PJ_AH + cso[r], Ah_b + cgi[r]);
            cp16(st + PJ_AL + cso[r], Al_b + cgi[r]);
            cp16(st + PJ_BH + cso[r], Bh_b + cgi[r]);
            cp16(st + PJ_BL + cso[r], Bl_b + cgi[r]);
        }
        CP_COMMIT();
    }

    for (int s = 0; s < PJ_NST; s++) {
        if (s + 1 < PJ_NST) {
            const uint32_t st = sb + ((s + 1) & 1) * PJ_STAGE;
            const size_t koff = (size_t)(s + 1) * 64;
#pragma unroll
            for (int r = 0; r < 4; r++) {
                cp16(st + PJ_AH + cso[r], Ah_b + cgi[r] + koff);
                cp16(st + PJ_AL + cso[r], Al_b + cgi[r] + koff);
                cp16(st + PJ_BH + cso[r], Bh_b + cgi[r] + koff);
                cp16(st + PJ_BL + cso[r], Bl_b + cgi[r] + koff);
            }
            CP_COMMIT();
            CP_WAIT1();
        } else {
            CP_WAIT0();
        }
        __syncthreads();

        const uint32_t st = sb + (s & 1) * PJ_STAGE;
#pragma unroll
        for (int ks = 0; ks < 4; ks++) {
            const int k0b = ks * 32;
            uint32_t Ahf[4][4], Alf[4][4], Bhf[4][2], Blf[4][2];
#pragma unroll
            for (int mt = 0; mt < 4; mt++)
                ldsm_x4(Ahf[mt], st + PJ_AH + (uint32_t)((rowA + mt * 16) * 128) + (uint32_t)((k0b + colA) ^ maskA));
#pragma unroll
            for (int nt = 0; nt < 4; nt++) {
                ldsm_x2(Bhf[nt], st + PJ_BH + (uint32_t)((rowB + nt * 8) * 128) + (uint32_t)((k0b + colB) ^ maskB));
                ldsm_x2(Blf[nt], st + PJ_BL + (uint32_t)((rowB + nt * 8) * 128) + (uint32_t)((k0b + colB) ^ maskB));
            }
#pragma unroll
            for (int mt = 0; mt < 4; mt++)
#pragma unroll
                for (int nt = 0; nt < 4; nt++)
                    mma_bf16(acc[mt][nt], Ahf[mt], Bhf[nt]);
#pragma unroll
            for (int mt = 0; mt < 4; mt++)
                ldsm_x4(Alf[mt], st + PJ_AL + (uint32_t)((rowA + mt * 16) * 128) + (uint32_t)((k0b + colA) ^ maskA));
#pragma unroll
            for (int mt = 0; mt < 4; mt++)
#pragma unroll
                for (int nt = 0; nt < 4; nt++)
                    mma_bf16(acc[mt][nt], Ahf[mt], Blf[nt]);
#pragma unroll
            for (int mt = 0; mt < 4; mt++)
#pragma unroll
                for (int nt = 0; nt < 4; nt++)
                    mma_bf16(acc[mt][nt], Alf[mt], Bhf[nt]);
        }
        __syncthreads();
    }

    const int r0 = lane >> 2;
    const int c0 = (lane & 3) * 2;
#pragma unroll
    for (int mt = 0; mt < 4; mt++) {
        const int mrow = m0 + warp_m * 64 + mt * 16 + r0;
#pragma unroll
        for (int nt = 0; nt < 4; nt++) {
            const int ncol = n0 + warp_n * 32 + nt * 8 + c0;
#pragma unroll
            for (int half = 0; half < 2; half++) {
                const int m = mrow + half * 8;
                float2 v = half ? make_float2(acc[mt][nt][2], acc[mt][nt][3])
                                : make_float2(acc[mt][nt][0], acc[mt][nt][1]);
                if (bias)  { v.x += bias[ncol]; v.y += bias[ncol + 1]; }
                if (resid) {
                    float2 rr = *(const float2*)(resid + (size_t)m * N + ncol);
                    v.x += rr.x; v.y += rr.y;
                }
                *(float2*)(C + (size_t)m * N + ncol) = v;
            }
        }
    }
}

// ======================= prep q (fold mixing*scale, single bf16) ===========
__global__ __launch_bounds__(256)
void prep_q_kernel(const float* __restrict__ q, const float* __restrict__ mixing,
                   __nv_bfloat16* __restrict__ qm)
{
    const int bh = blockIdx.y;
    const int b = bh >> 4, h = bh & 15;
    const size_t i4 = (size_t)blockIdx.x * 256 + threadIdx.x;
    const int s = (int)(i4 >> 8);
    const int c4 = (int)(i4 & 255);
    float4 v = *(const float4*)(q + ((size_t)b * SS + s) * DKK + c4 * 4);
    float4 m = *(const float4*)(mixing + (size_t)h * DKK + c4 * 4);
    v.x *= m.x * SCALE; v.y *= m.y * SCALE; v.z *= m.z * SCALE; v.w *= m.w * SCALE;
    uint2 p;
    p.x = pack2(__float2bfloat16(v.x), __float2bfloat16(v.y));
    p.y = pack2(__float2bfloat16(v.z), __float2bfloat16(v.w));
    *(uint2*)(qm + ((size_t)bh * SS + s) * DKK + c4 * 4) = p;
}

// ======================= prep V^T per head (bf16 hi/lo) ====================
__global__ __launch_bounds__(256)
void prep_vt_kernel(const float* __restrict__ v,
                    __nv_bfloat16* __restrict__ vth, __nv_bfloat16* __restrict__ vtl)
{
    const int tid = threadIdx.x;
    const int bh = blockIdx.z;
    const int b = bh >> 4, h = bh & 15;
    const int j = blockIdx.x * 64 + (tid & 63);
    const int vvg = blockIdx.y * 4 + (tid >> 6);
    float4 v4 = *(const float4*)(v + ((size_t)b * SS + j) * DVV + h * HEADV + vvg * 4);
#pragma unroll
    for (int e = 0; e < 4; e++) {
        float val = (&v4.x)[e];
        __nv_bfloat16 hh = __float2bfloat16(val);
        __nv_bfloat16 ll = __float2bfloat16(val - __bfloat162float(hh));
        const size_t o = ((size_t)bh * HEADV + vvg * 4 + e) * SS + j;
        vth[o] = hh; vtl[o] = ll;
    }
}

__global__ __launch_bounds__(256)
void cbt_kernel(const float* __restrict__ cb, float* __restrict__ cbt)
{
    const int bh = blockIdx.y;
    const int b = bh >> 4, h = bh & 15;
    const int j = blockIdx.x * 256 + threadIdx.x;
    cbt[(size_t)bh * SS + j] = cb[((size_t)b * SS + j) * HH + h] * SCALE;
}

// ======================= HMMA scores GEMM (128x256, single-pass bf16) ======
#define SC_A  0
#define SC_B  16384
#define SC_STAGE 49152          // 48 KB per stage
#define SC_NST 16

__global__ __launch_bounds__(256, 1)
void scores_kernel(const __nv_bfloat16* __restrict__ qm, const __nv_bfloat16* __restrict__ kb,
                   float* __restrict__ scores)
{
    extern __shared__ __align__(1024) char smem[];
    const uint32_t sb = smem_to_u32(smem);

    const int tid = threadIdx.x;
    const int wid = tid >> 5;
    const int lane = tid & 31;
    const int bh = blockIdx.z;
    const int b = bh >> 4;
    const int i0 = blockIdx.y * 128;
    const int j0 = blockIdx.x * 256;
    const int warp_m = wid >> 2;     // 0..1 (64 rows)
    const int warp_n = wid & 3;      // 0..3 (64 cols)

    const __nv_bfloat16* qm_b = qm + ((size_t)bh * SS + i0) * DKK;
    const __nv_bfloat16* kb_b = kb + ((size_t)b * SS + j0) * DKK;

    float acc[4][8][4];
#pragma unroll
    for (int mt = 0; mt < 4; mt++)
#pragma unroll
        for (int nn = 0; nn < 8; nn++)
#pragma unroll
            for (int e = 0; e < 4; e++) acc[mt][nn][e] = 0.f;

    int csoA[4];  size_t cgiA[4];
#pragma unroll
    for (int r = 0; r < 4; r++) {
        const int chunk = tid + 256 * r;
        const int row = chunk >> 3, cc = chunk & 7;
        csoA[r] = row * 128 + ((cc * 16) ^ ((row & 7) << 4));
        cgiA[r] = (size_t)row * DKK + cc * 8;
    }
    int csoB[8];  size_t cgiB[8];
#pragma unroll
    for (int r = 0; r < 8; r++) {
        const int chunk = tid + 256 * r;
        const int row = chunk >> 3, cc = chunk & 7;
        csoB[r] = row * 128 + ((cc * 16) ^ ((row & 7) << 4));
        cgiB[r] = (size_t)row * DKK + cc * 8;
    }

    {
        const uint32_t st = sb;
#pragma unroll
        for (int r = 0; r < 4; r++)
            cp16(st + SC_A + csoA[r], qm_b + cgiA[r]);
#pragma unroll
        for (int r = 0; r < 8; r++)
            cp16(st + SC_B + csoB[r], kb_b + cgiB[r]);
        CP_COMMIT();
    }

    for (int s = 0; s < SC_NST; s++) {
        if (s + 1 < SC_NST) {
            const uint32_t st = sb + ((s + 1) & 1) * SC_STAGE;
            const size_t koff = (size_t)(s + 1) * 64;
#pragma unroll
            for (int r = 0; r < 4; r++)
                cp16(st + SC_A + csoA[r], qm_b + cgiA[r] + koff);
#pragma unroll
            for (int r = 0; r < 8; r++)
                cp16(st + SC_B + csoB[r], kb_b + cgiB[r] + koff);
            CP_COMMIT();
            CP_WAIT1();
        } else {
            CP_WAIT0();
        }
        __syncthreads();

        const uint32_t st = sb + (s & 1) * SC_STAGE;
#pragma unroll
        for (int ks = 0; ks < 4; ks++) {
            const int k0b = ks * 32;
            uint32_t Af[4][4];
#pragma unroll
            for (int mt = 0; mt < 4; mt++) {
                const int rowA = warp_m * 64 + mt * 16 + (lane & 15);
                const uint32_t cA = (uint32_t)((k0b + ((lane >> 4) << 4)) ^ ((rowA & 7) << 4));
                ldsm_x4(Af[mt], st + SC_A + (uint32_t)(rowA * 128) + cA);
            }
#pragma unroll
            for (int ng = 0; ng < 4; ng++) {
                const int rowB = warp_n * 64 + ng * 16 + (lane & 7) + ((lane & 16) >> 1);
                const uint32_t cB = (uint32_t)((k0b + (((lane >> 3) & 1) << 4)) ^ ((rowB & 7) << 4));
                uint32_t B4[4];
                ldsm_x4(B4, st + SC_B + (uint32_t)(rowB * 128) + cB);
#pragma unroll
                for (int mt = 0; mt < 4; mt++) {
                    mma_bf16(acc[mt][ng * 2 + 0], Af[mt], B4 + 0);
                    mma_bf16(acc[mt][ng * 2 + 1], Af[mt], B4 + 2);
                }
            }
        }
        __syncthreads();
    }

    const int r0 = lane >> 2;
    const int c0 = (lane & 3) * 2;
#pragma unroll
    for (int mt = 0; mt < 4; mt++) {
        float* base = scores + ((size_t)bh * SS + i0 + warp_m * 64 + mt * 16 + r0) * SS
                             + j0 + warp_n * 64 + c0;
#pragma unroll
        for (int nn = 0; nn < 8; nn++) {
            *(float2*)(base + nn * 8) = make_float2(acc[mt][nn][0], acc[mt][nn][1]);
            *(float2*)(base + 8 * SS + nn * 8) = make_float2(acc[mt][nn][2], acc[mt][nn][3]);
        }
    }
}

// ======================= fused softmax + PV (flash over scores) ============
#define FP_PH 0
#define FP_PL 32768
#define FP_VH 65536
#define FP_VL 81920
#define FP_M  98304
#define FP_SC 98816
#define FP_L  99328
#define FP_SMEM 99840

__global__ __launch_bounds__(256, 1)
void fused_pv_kernel(const float* __restrict__ scores, const float* __restrict__ cbt,
                     const __nv_bfloat16* __restrict__ vth, const __nv_bfloat16* __restrict__ vtl,
                     float* __restrict__ ctx)
{
    extern __shared__ __align__(1024) char sm[];
    const uint32_t sb = smem_to_u32(sm);
    float* sm_m  = (float*)(sm + FP_M);
    float* sm_sc = (float*)(sm + FP_SC);
    float* sm_l  = (float*)(sm + FP_L);

    const int tid = threadIdx.x;
    const int wid = tid >> 5;
    const int lane = tid & 31;
    const int bh = blockIdx.y;
    const int b = bh >> 4, h = bh & 15;
    const int i0 = blockIdx.x * 128;

    if (tid < 128) { sm_m[tid] = -INFINITY; sm_l[tid] = 0.f; }

    float acc[8][4];
#pragma unroll
    for (int nn = 0; nn < 8; nn++)
#pragma unroll
        for (int e = 0; e < 4; e++) acc[nn][e] = 0.f;

    const int srow = tid >> 1;
    const int sch = tid & 1;
    const float* sptr = scores + ((size_t)bh * SS + i0 + srow) * SS + sch * 64;
    const float* cptr = cbt + (size_t)bh * SS + sch * 64;

    const int m0 = wid * 16;
    const int r0 = m0 + (lane >> 2);
    const int r1 = r0 + 8;

    __syncthreads();

    for (int j0 = 0; j0 < SS; j0 += 128) {
#pragma unroll
        for (int r = 0; r < 4; r++) {
            const int id = tid + 256 * r;
            const int row = id >> 4, cc = id & 15;
            const uint32_t so = (uint32_t)(row * 256 + ((cc * 16) ^ ((row & 7) << 4)));
            const size_t gi = ((size_t)bh * HEADV + row) * SS + j0 + cc * 8;
            cp16(sb + FP_VH + so, vth + gi);
            cp16(sb + FP_VL + so, vtl + gi);
        }
        CP_COMMIT();

        float vals[64];
        float tmax = -INFINITY;
#pragma unroll
        for (int c4 = 0; c4 < 16; c4++) {
            float4 s4 = *(const float4*)(sptr + j0 + c4 * 4);
            float4 cb4 = *(const float4*)(cptr + j0 + c4 * 4);
            s4.x += cb4.x; s4.y += cb4.y; s4.z += cb4.z; s4.w += cb4.w;
            vals[c4 * 4 + 0] = s4.x; vals[c4 * 4 + 1] = s4.y;
            vals[c4 * 4 + 2] = s4.z; vals[c4 * 4 + 3] = s4.w;
            tmax = fmaxf(tmax, fmaxf(fmaxf(s4.x, s4.y), fmaxf(s4.z, s4.w)));
        }
        tmax = fmaxf(tmax, __shfl_xor_sync(0xffffffffu, tmax, 1));
        const float mold = sm_m[srow];
        const float mnew = fmaxf(mold, tmax);
        const float scl = __expf(mold - mnew);
        float rsum = 0.f;
#pragma unroll
        for (int c = 0; c < 64; c++) { vals[c] = __expf(vals[c] - mnew); rsum += vals[c]; }
        rsum += __shfl_xor_sync(0xffffffffu, rsum, 1);
        if (sch == 0) {
            sm_l[srow] = sm_l[srow] * scl + rsum;
            sm_m[srow] = mnew;
            sm_sc[srow] = scl;
        }
#pragma unroll
        for (int c4 = 0; c4 < 16; c4++) {
            float p0 = vals[c4 * 4 + 0], p1 = vals[c4 * 4 + 1];
            float p2 = vals[c4 * 4 + 2], p3 = vals[c4 * 4 + 3];
            __nv_bfloat16 h0 = __float2bfloat16(p0), h1 = __float2bfloat16(p1);
            __nv_bfloat16 h2 = __float2bfloat16(p2), h3 = __float2bfloat16(p3);
            uint2 hp, lp;
            hp.x = pack2(h0, h1); hp.y = pack2(h2, h3);
            lp.x = pack2(__float2bfloat16(p0 - __bfloat162float(h0)),
                         __float2bfloat16(p1 - __bfloat162float(h1)));
            lp.y = pack2(__float2bfloat16(p2 - __bfloat162float(h2)),
                         __float2bfloat16(p3 - __bfloat162float(h3)));
            const uint32_t colbyte = (uint32_t)(sch * 128 + c4 * 8);
            const uint32_t off = (uint32_t)(srow * 256) + (colbyte ^ ((srow & 7) << 4));
            *(uint2*)(sm + FP_PH + off) = hp;
            *(uint2*)(sm + FP_PL + off) = lp;
        }
        CP_WAIT0();
        __syncthreads();

        const float s0 = sm_sc[r0];
        const float s1 = sm_sc[r1];
#pragma unroll
        for (int nn = 0; nn < 8; nn++) {
            acc[nn][0] *= s0; acc[nn][1] *= s0;
            acc[nn][2] *= s1; acc[nn][3] *= s1;
        }
#pragma unroll
        for (int ks = 0; ks < 8; ks++) {
            const int k0b = ks * 32;
            uint32_t Ah4[4], Al4[4];
            const int rowa = m0 + (lane & 15);
            const uint32_t cA = (uint32_t)((k0b + ((lane >> 4) << 4)) ^ ((rowa & 7) << 4));
            ldsm_x4(Ah4, sb + FP_PH + (uint32_t)(rowa * 256) + cA);
            ldsm_x4(Al4, sb + FP_PL + (uint32_t)(rowa * 256) + cA);
#pragma unroll
            for (int ng = 0; ng < 4; ng++) {
                const int rowb = ng * 16 + (lane & 7) + ((lane & 16) >> 1);
                const uint32_t cB = (uint32_t)((k0b + (((lane >> 3) & 1) << 4)) ^ ((rowb & 7) << 4));
                uint32_t Bh4[4], Bl4[4];
                ldsm_x4(Bh4, sb + FP_VH + (uint32_t)(rowb * 256) + cB);
                mma_bf16(acc[ng * 2 + 0], Ah4, Bh4 + 0);
                mma_bf16(acc[ng * 2 + 1], Ah4, Bh4 + 2);
                mma_bf16(acc[ng * 2 + 0], Al4, Bh4 + 0);
                mma_bf16(acc[ng * 2 + 1], Al4, Bh4 + 2);
                ldsm_x4(Bl4, sb + FP_VL + (uint32_t)(rowb * 256) + cB);
                mma_bf16(acc[ng * 2 + 0], Ah4, Bl4 + 0);
                mma_bf16(acc[ng * 2 + 1], Ah4, Bl4 + 2);
            }
        }
        __syncthreads();
    }

    const float inv0 = 1.f / sm_l[r0];
    const float inv1 = 1.f / sm_l[r1];
    const int c0 = (lane & 3) * 2;
#pragma unroll
    for (int nn = 0; nn < 8; nn++) {
        const int col = h * HEADV + nn * 8 + c0;
        *(float2*)(ctx + ((size_t)b * SS + i0 + r0) * DVV + col) =
            make_float2(acc[nn][0] * inv0, acc[nn][1] * inv0);
        *(float2*)(ctx + ((size_t)b * SS + i0 + r1) * DVV + col) =
            make_float2(acc[nn][2] * inv1, acc[nn][3] * inv1);
    }
}

// ======================= LayerNorm =========================================
__global__ __launch_bounds__(256)
void ln_kernel(const float* __restrict__ res, const float* __restrict__ gamma,
               const float* __restrict__ beta, float* __restrict__ out)
{
    const int row = blockIdx.x;
    const int c = threadIdx.x * 4;
    const float4 v = *(const float4*)(res + (size_t)row * DOUT + c);
    float s  = v.x + v.y + v.z + v.w;
    float s2 = v.x * v.x + v.y * v.y + v.z * v.z + v.w * v.w;
#pragma unroll
    for (int o = 16; o >= 1; o >>= 1) {
        s  += __shfl_xor_sync(0xffffffffu, s,  o);
        s2 += __shfl_xor_sync(0xffffffffu, s2, o);
    }
    __shared__ float sh[8], sh2[8];
    __shared__ float mu_s, inv_s;
    const int w = threadIdx.x >> 5;
    if ((threadIdx.x & 31) == 0) { sh[w] = s; sh2[w] = s2; }
    __syncthreads();
    if (threadIdx.x == 0) {
        float S = 0.f, S2 = 0.f;
#pragma unroll
        for (int i = 0; i < 8; i++) { S += sh[i]; S2 += sh2[i]; }
        const float mu = S * (1.f / DOUT);
        const float var = S2 * (1.f / DOUT) - mu * mu;
        mu_s = mu; inv_s = rsqrtf(var + LN_EPS);
    }
    __syncthreads();
    const float mu = mu_s, inv = inv_s;
    const float4 g  = *(const float4*)(gamma + c);
    const float4 bt = *(const float4*)(beta + c);
    float4 o;
    o.x = (v.x - mu) * inv * g.x + bt.x;
    o.y = (v.y - mu) * inv * g.y + bt.y;
    o.z = (v.z - mu) * inv * g.z + bt.z;
    o.w = (v.w - mu) * inv * g.w + bt.w;
    *(float4*)(out + (size_t)row * DOUT + c) = o;
}

// ===========================================================================
extern "C" void kernel_launch(void* const* d_in, const int* in_sizes, int n_in,
                              void* d_out, int out_size)
{
    const float* x      = (const float*)d_in[0];
    const float* Wq     = (const float*)d_in[1];
    const float* Wk     = (const float*)d_in[2];
    const float* Wcb    = (const float*)d_in[3];
    const float* Wv     = (const float*)d_in[4];
    const float* bv     = (const float*)d_in[5];
    const float* mixing = (const float*)d_in[6];
    const float* Wd     = (const float*)d_in[7];
    const float* bd     = (const float*)d_in[8];
    const float* gamma  = (const float*)d_in[9];
    const float* beta   = (const float*)d_in[10];
    float* out = (float*)d_out;

    float *q, *k, *v, *ctx, *res, *cb, *cbt, *scores;
    __nv_bfloat16 *qm, *kb, *xh, *xl, *wh, *wl, *vth, *vtl, *cxh, *cxl;
    cudaGetSymbolAddress((void**)&q,      g_q);
    cudaGetSymbolAddress((void**)&k,      g_k);
    cudaGetSymbolAddress((void**)&v,      g_v);
    cudaGetSymbolAddress((void**)&ctx,    g_ctx);
    cudaGetSymbolAddress((void**)&res,    g_res);
    cudaGetSymbolAddress((void**)&cb,     g_cb);
    cudaGetSymbolAddress((void**)&cbt,    g_cbt);
    cudaGetSymbolAddress((void**)&scores, g_scores);
    cudaGetSymbolAddress((void**)&qm,     g_qm);
    cudaGetSymbolAddress((void**)&kb,     g_kb);
    cudaGetSymbolAddress((void**)&xh,     g_xh);
    cudaGetSymbolAddress((void**)&xl,     g_xl);
    cudaGetSymbolAddress((void**)&wh,     g_wh);
    cudaGetSymbolAddress((void**)&wl,     g_wl);
    cudaGetSymbolAddress((void**)&vth,    g_vth);
    cudaGetSymbolAddress((void**)&vtl,    g_vtl);
    cudaGetSymbolAddress((void**)&cxh,    g_cxh);
    cudaGetSymbolAddress((void**)&cxl,    g_cxl);

    cudaFuncSetAttribute(scores_kernel,   cudaFuncAttributeMaxDynamicSharedMemorySize, 2 * SC_STAGE);
    cudaFuncSetAttribute(hmma_nt_kernel,  cudaFuncAttributeMaxDynamicSharedMemorySize, 2 * PJ_STAGE);
    cudaFuncSetAttribute(fused_pv_kernel, cudaFuncAttributeMaxDynamicSharedMemorySize, FP_SMEM);

    const size_t WSZ = 1024 * 1024;

    // splits
    split_kernel<<<MROWS * DIN / 1024, 256>>>(x, xh, xl);
    split_kernel<<<WSZ / 1024, 256>>>(Wq, wh + 0 * WSZ, wl + 0 * WSZ);
    split_kernel<<<WSZ / 1024, 256>>>(Wk, wh + 1 * WSZ, wl + 1 * WSZ);
    split_kernel<<<WSZ / 1024, 256>>>(Wv, wh + 2 * WSZ, wl + 2 * WSZ);
    split_kernel<<<WSZ / 1024, 256>>>(Wd, wh + 3 * WSZ, wl + 3 * WSZ);

    // projections (HMMA)
    dim3 gProj(DKK / 128, MROWS / 128);    // (8, 32)
    hmma_nt_kernel<<<gProj, 256, 2 * PJ_STAGE>>>(xh, xl, wh + 0 * WSZ, wl + 0 * WSZ, nullptr, nullptr, q, DKK);
    hmma_nt_kernel<<<gProj, 256, 2 * PJ_STAGE>>>(xh, xl, wh + 1 * WSZ, wl + 1 * WSZ, nullptr, nullptr, k, DKK);
    hmma_nt_kernel<<<gProj, 256, 2 * PJ_STAGE>>>(xh, xl, wh + 2 * WSZ, wl + 2 * WSZ, bv, nullptr, v, DVV);
    gemm_nt_kernel<<<dim3(1, MROWS / 64), 256>>>(x, Wcb, cb, MROWS, HH, DIN);

    // attention preps
    cvt_bf_kernel<<<MROWS * DKK / 1024, 256>>>(k, kb);
    prep_q_kernel<<<dim3(SS * DKK / 4 / 256, BH), 256>>>(q, mixing, qm);
    prep_vt_kernel<<<dim3(SS / 64, HEADV / 16, BH), 256>>>(v, vth, vtl);
    cbt_kernel<<<dim3(SS / 256, BH), 256>>>(cb, cbt);

    // attention
    scores_kernel<<<dim3(SS / 256, SS / 128, BH), 256, 2 * SC_STAGE>>>(qm, kb, scores);
    fused_pv_kernel<<<dim3(SS / 128, BH), 256, FP_SMEM>>>(scores, cbt, vth, vtl, ctx);

    // output projection + residual + LN
    split_kernel<<<MROWS * DVV / 1024, 256>>>(ctx, cxh, cxl);
    hmma_nt_kernel<<<gProj, 256, 2 * PJ_STAGE>>>(cxh, cxl, wh + 3 * WSZ, wl + 3 * WSZ, bd, x, res, DOUT);
    ln_kernel<<<MROWS, 256>>>(res, gamma, beta, out);
}

// round 10
// speedup vs baseline: 2.5531x; 1.2830x over previous
#include <cuda_runtime.h>
#include <cuda_bf16.h>
#include <math.h>
#include <stdint.h>

// Problem constants
#define BB 2
#define SS 2048
#define DIN 1024
#define HH 16
#define DKK 1024
#define DVV 1024
#define DOUT 1024
#define MROWS (BB*SS)          // 4096
#define BH (BB*HH)             // 32
#define HEADV 64
#define SCALE 0.125f
#define LN_EPS 1e-5f

// Scratch
__device__ float g_q  [(size_t)MROWS * DKK];
__device__ float g_k  [(size_t)MROWS * DKK];
__device__ float g_v  [(size_t)MROWS * DVV];
__device__ float g_ctx[(size_t)MROWS * DVV];
__device__ float g_res[(size_t)MROWS * DOUT];
__device__ float g_cbt[(size_t)BH * SS];
__device__ __nv_bfloat16 g_scoresb[(size_t)BH * SS * SS];   // 268 MB
__device__ __nv_bfloat16 g_qm[(size_t)BH * SS * DKK];
__device__ __nv_bfloat16 g_kb[(size_t)MROWS * DKK];
__device__ __nv_bfloat16 g_xb[(size_t)MROWS * DIN];
__device__ __nv_bfloat16 g_wb[(size_t)4 * 1024 * 1024];
__device__ __nv_bfloat16 g_vt[(size_t)BH * HEADV * SS];
__device__ __nv_bfloat16 g_cxb[(size_t)MROWS * DVV];

// ======================= helpers ===========================================
__device__ __forceinline__ uint32_t smem_to_u32(const void* p) {
    uint32_t a;
    asm("{ .reg .u64 t; cvta.to.shared.u64 t, %1; cvt.u32.u64 %0, t; }" : "=r"(a) : "l"(p));
    return a;
}
__device__ __forceinline__ void cp16(uint32_t s, const void* g) {
    asm volatile("cp.async.cg.shared.global [%0], [%1], 16;" :: "r"(s), "l"(g));
}
#define CP_COMMIT() asm volatile("cp.async.commit_group;" ::: "memory")
#define CP_WAIT1()  asm volatile("cp.async.wait_group 1;" ::: "memory")
#define CP_WAIT0()  asm volatile("cp.async.wait_group 0;" ::: "memory")

__device__ __forceinline__ void ldsm_x4(uint32_t* r, uint32_t addr) {
    asm volatile("ldmatrix.sync.aligned.m8n8.x4.shared.b16 {%0,%1,%2,%3}, [%4];"
        : "=r"(r[0]), "=r"(r[1]), "=r"(r[2]), "=r"(r[3]) : "r"(addr));
}
__device__ __forceinline__ void ldsm_x2(uint32_t* r, uint32_t addr) {
    asm volatile("ldmatrix.sync.aligned.m8n8.x2.shared.b16 {%0,%1}, [%2];"
        : "=r"(r[0]), "=r"(r[1]) : "r"(addr));
}
__device__ __forceinline__ void mma_bf16(float* c, const uint32_t* a, const uint32_t* b) {
    asm volatile("mma.sync.aligned.m16n8k16.row.col.f32.bf16.bf16.f32 "
        "{%0,%1,%2,%3}, {%4,%5,%6,%7}, {%8,%9}, {%0,%1,%2,%3};"
        : "+f"(c[0]), "+f"(c[1]), "+f"(c[2]), "+f"(c[3])
        : "r"(a[0]), "r"(a[1]), "r"(a[2]), "r"(a[3]), "r"(b[0]), "r"(b[1]));
}
__device__ __forceinline__ uint32_t pack2(__nv_bfloat16 a, __nv_bfloat16 b) {
    return (uint32_t)__bfloat16_as_ushort(a) | ((uint32_t)__bfloat16_as_ushort(b) << 16);
}
__device__ __forceinline__ float2 bf2_to_f2(uint32_t u) {
    float2 r;
    r.x = __bfloat162float(__ushort_as_bfloat16((unsigned short)(u & 0xffffu)));
    r.y = __bfloat162float(__ushort_as_bfloat16((unsigned short)(u >> 16)));
    return r;
}

// ======================= fp32 -> bf16 convert ==============================
__global__ __launch_bounds__(256)
void cvt_bf_kernel(const float* __restrict__ in, __nv_bfloat16* __restrict__ o)
{
    const size_t i4 = (size_t)blockIdx.x * 256 + threadIdx.x;
    float4 v = *(const float4*)(in + i4 * 4);
    uint2 p;
    p.x = pack2(__float2bfloat16(v.x), __float2bfloat16(v.y));
    p.y = pack2(__float2bfloat16(v.z), __float2bfloat16(v.w));
    *(uint2*)(o + i4 * 4) = p;
}

// ======================= content bias (direct to cbt) ======================
__global__ __launch_bounds__(256)
void cb_kernel(const float* __restrict__ x, const float* __restrict__ Wcb,
               float* __restrict__ cbt)
{
    __shared__ float xs[16][132];
    const int tid = threadIdx.x;
    const int r = tid >> 4;
    const int h = tid & 15;
    const int row0 = blockIdx.x * 16;

    float acc = 0.f;
    for (int c0 = 0; c0 < DIN; c0 += 128) {
        __syncthreads();
#pragma unroll
        for (int i = 0; i < 2; i++) {
            const int id = tid + i * 256;
            const int rr = id >> 5, cc = (id & 31) * 4;
            *(float4*)&xs[rr][cc] = *(const float4*)(x + (size_t)(row0 + rr) * DIN + c0 + cc);
        }
        __syncthreads();
        const float4* wp = (const float4*)(Wcb + (size_t)h * DIN + c0);
#pragma unroll
        for (int i = 0; i < 32; i++) {
            float4 w = wp[i];
            float4 xv = *(const float4*)&xs[r][i * 4];
            acc += xv.x * w.x + xv.y * w.y + xv.z * w.z + xv.w * w.w;
        }
    }
    const int row = row0 + r;
    const int b = row >> 11, s = row & 2047;
    cbt[((size_t)(b * HH + h)) * SS + s] = acc * SCALE;
}

// ======================= 1-pass HMMA NT GEMM (projections) =================
#define P1_A 0
#define P1_B 16384
#define P1_STAGE 32768
#define P1_NST 16

__global__ __launch_bounds__(256)
void hmma1_nt_kernel(const __nv_bfloat16* __restrict__ Ap, const __nv_bfloat16* __restrict__ Bp,
                     const float* __restrict__ bias, const float* __restrict__ resid,
                     float* __restrict__ C, int N)
{
    extern __shared__ __align__(1024) char smem[];
    const uint32_t sb = smem_to_u32(smem);

    const int tid = threadIdx.x;
    const int wid = tid >> 5;
    const int lane = tid & 31;
    const int m0 = blockIdx.y * 128;
    const int n0 = blockIdx.x * 128;
    const int warp_m = wid >> 2;
    const int warp_n = wid & 3;

    const __nv_bfloat16* A_b = Ap + (size_t)m0 * DKK;
    const __nv_bfloat16* B_b = Bp + (size_t)n0 * DKK;

    float acc[4][4][4];
#pragma unroll
    for (int mt = 0; mt < 4; mt++)
#pragma unroll
        for (int nt = 0; nt < 4; nt++)
#pragma unroll
            for (int e = 0; e < 4; e++) acc[mt][nt][e] = 0.f;

    int cso[4];
    size_t cgi[4];
#pragma unroll
    for (int r = 0; r < 4; r++) {
        const int chunk = tid + 256 * r;
        const int row = chunk >> 3;
        const int cc = chunk & 7;
        cso[r] = row * 128 + ((cc * 16) ^ ((row & 7) << 4));
        cgi[r] = (size_t)row * DKK + cc * 8;
    }

    const int rowA = warp_m * 64 + (lane & 15);
    const int colA = ((lane >> 4) << 4);
    const uint32_t maskA = (rowA & 7) << 4;
    const int rowB = warp_n * 32 + (lane & 7);
    const int colB = ((lane >> 3) & 1) << 4;
    const uint32_t maskB = (rowB & 7) << 4;

    {
        const uint32_t st = sb;
#pragma unroll
        for (int r = 0; r < 4; r++) {
            cp16(st + P1_A + cso[r], A_b + cgi[r]);
            cp16(st + P1_B + cso[r], B_b + cgi[r]);
        }
        CP_COMMIT();
    }

    for (int s = 0; s < P1_NST; s++) {
        if (s + 1 < P1_NST) {
            const uint32_t st = sb + ((s + 1) & 1) * P1_STAGE;
            const size_t koff = (size_t)(s + 1) * 64;
#pragma unroll
            for (int r = 0; r < 4; r++) {
                cp16(st + P1_A + cso[r], A_b + cgi[r] + koff);
                cp16(st + P1_B + cso[r], B_b + cgi[r] + koff);
            }
            CP_COMMIT();
            CP_WAIT1();
        } else {
            CP_WAIT0();
        }
        __syncthreads();

        const uint32_t st = sb + (s & 1) * P1_STAGE;
#pragma unroll
        for (int ks = 0; ks < 4; ks++) {
            const int k0b = ks * 32;
            uint32_t Af[4][4], Bf[4][2];
#pragma unroll
            for (int mt = 0; mt < 4; mt++)
                ldsm_x4(Af[mt], st + P1_A + (uint32_t)((rowA + mt * 16) * 128) + (uint32_t)((k0b + colA) ^ maskA));
#pragma unroll
            for (int nt = 0; nt < 4; nt++)
                ldsm_x2(Bf[nt], st + P1_B + (uint32_t)((rowB + nt * 8) * 128) + (uint32_t)((k0b + colB) ^ maskB));
#pragma unroll
            for (int mt = 0; mt < 4; mt++)
#pragma unroll
                for (int nt = 0; nt < 4; nt++)
                    mma_bf16(acc[mt][nt], Af[mt], Bf[nt]);
        }
        __syncthreads();
    }

    const int r0 = lane >> 2;
    const int c0 = (lane & 3) * 2;
#pragma unroll
    for (int mt = 0; mt < 4; mt++) {
        const int mrow = m0 + warp_m * 64 + mt * 16 + r0;
#pragma unroll
        for (int nt = 0; nt < 4; nt++) {
            const int ncol = n0 + warp_n * 32 + nt * 8 + c0;
#pragma unroll
            for (int half = 0; half < 2; half++) {
                const int m = mrow + half * 8;
                float2 v = half ? make_float2(acc[mt][nt][2], acc[mt][nt][3])
                                : make_float2(acc[mt][nt][0], acc[mt][nt][1]);
                if (bias)  { v.x += bias[ncol]; v.y += bias[ncol + 1]; }
                if (resid) {
                    float2 rr = *(const float2*)(resid + (size_t)m * N + ncol);
                    v.x += rr.x; v.y += rr.y;
                }
                *(float2*)(C + (size_t)m * N + ncol) = v;
            }
        }
    }
}

// ======================= prep q (fold mixing*scale, single bf16) ===========
__global__ __launch_bounds__(256)
void prep_q_kernel(const float* __restrict__ q, const float* __restrict__ mixing,
                   __nv_bfloat16* __restrict__ qm)
{
    const int bh = blockIdx.y;
    const int b = bh >> 4, h = bh & 15;
    const size_t i4 = (size_t)blockIdx.x * 256 + threadIdx.x;
    const int s = (int)(i4 >> 8);
    const int c4 = (int)(i4 & 255);
    float4 v = *(const float4*)(q + ((size_t)b * SS + s) * DKK + c4 * 4);
    float4 m = *(const float4*)(mixing + (size_t)h * DKK + c4 * 4);
    v.x *= m.x * SCALE; v.y *= m.y * SCALE; v.z *= m.z * SCALE; v.w *= m.w * SCALE;
    uint2 p;
    p.x = pack2(__float2bfloat16(v.x), __float2bfloat16(v.y));
    p.y = pack2(__float2bfloat16(v.z), __float2bfloat16(v.w));
    *(uint2*)(qm + ((size_t)bh * SS + s) * DKK + c4 * 4) = p;
}

// ======================= prep V^T per head (single bf16) ===================
__global__ __launch_bounds__(256)
void prep_vt_kernel(const float* __restrict__ v, __nv_bfloat16* __restrict__ vt)
{
    const int tid = threadIdx.x;
    const int bh = blockIdx.z;
    const int b = bh >> 4, h = bh & 15;
    const int j = blockIdx.x * 64 + (tid & 63);
    const int vvg = blockIdx.y * 4 + (tid >> 6);
    float4 v4 = *(const float4*)(v + ((size_t)b * SS + j) * DVV + h * HEADV + vvg * 4);
#pragma unroll
    for (int e = 0; e < 4; e++) {
        vt[((size_t)bh * HEADV + vvg * 4 + e) * SS + j] = __float2bfloat16((&v4.x)[e]);
    }
}

// ======================= HMMA scores GEMM (128x256, 1-pass, bf16 out) ======
#define SC_A  0
#define SC_B  16384
#define SC_STAGE 49152          // 48 KB per stage
#define SC_NST 16

__global__ __launch_bounds__(256, 1)
void scores_kernel(const __nv_bfloat16* __restrict__ qm, const __nv_bfloat16* __restrict__ kb,
                   __nv_bfloat16* __restrict__ scoresb)
{
    extern __shared__ __align__(1024) char smem[];
    const uint32_t sb = smem_to_u32(smem);

    const int tid = threadIdx.x;
    const int wid = tid >> 5;
    const int lane = tid & 31;
    const int bh = blockIdx.z;
    const int b = bh >> 4;
    const int i0 = blockIdx.y * 128;
    const int j0 = blockIdx.x * 256;
    const int warp_m = wid >> 2;
    const int warp_n = wid & 3;

    const __nv_bfloat16* qm_b = qm + ((size_t)bh * SS + i0) * DKK;
    const __nv_bfloat16* kb_b = kb + ((size_t)b * SS + j0) * DKK;

    float acc[4][8][4];
#pragma unroll
    for (int mt = 0; mt < 4; mt++)
#pragma unroll
        for (int nn = 0; nn < 8; nn++)
#pragma unroll
            for (int e = 0; e < 4; e++) acc[mt][nn][e] = 0.f;

    int csoA[4];  size_t cgiA[4];
#pragma unroll
    for (int r = 0; r < 4; r++) {
        const int chunk = tid + 256 * r;
        const int row = chunk >> 3, cc = chunk & 7;
        csoA[r] = row * 128 + ((cc * 16) ^ ((row & 7) << 4));
        cgiA[r] = (size_t)row * DKK + cc * 8;
    }
    int csoB[8];  size_t cgiB[8];
#pragma unroll
    for (int r = 0; r < 8; r++) {
        const int chunk = tid + 256 * r;
        const int row = chunk >> 3, cc = chunk & 7;
        csoB[r] = row * 128 + ((cc * 16) ^ ((row & 7) << 4));
        cgiB[r] = (size_t)row * DKK + cc * 8;
    }

    {
        const uint32_t st = sb;
#pragma unroll
        for (int r = 0; r < 4; r++)
            cp16(st + SC_A + csoA[r], qm_b + cgiA[r]);
#pragma unroll
        for (int r = 0; r < 8; r++)
            cp16(st + SC_B + csoB[r], kb_b + cgiB[r]);
        CP_COMMIT();
    }

    for (int s = 0; s < SC_NST; s++) {
        if (s + 1 < SC_NST) {
            const uint32_t st = sb + ((s + 1) & 1) * SC_STAGE;
            const size_t koff = (size_t)(s + 1) * 64;
#pragma unroll
            for (int r = 0; r < 4; r++)
                cp16(st + SC_A + csoA[r], qm_b + cgiA[r] + koff);
#pragma unroll
            for (int r = 0; r < 8; r++)
                cp16(st + SC_B + csoB[r], kb_b + cgiB[r] + koff);
            CP_COMMIT();
            CP_WAIT1();
        } else {
            CP_WAIT0();
        }
        __syncthreads();

        const uint32_t st = sb + (s & 1) * SC_STAGE;
#pragma unroll
        for (int ks = 0; ks < 4; ks++) {
            const int k0b = ks * 32;
            uint32_t Af[4][4];
#pragma unroll
            for (int mt = 0; mt < 4; mt++) {
                const int rowA = warp_m * 64 + mt * 16 + (lane & 15);
                const uint32_t cA = (uint32_t)((k0b + ((lane >> 4) << 4)) ^ ((rowA & 7) << 4));
                ldsm_x4(Af[mt], st + SC_A + (uint32_t)(rowA * 128) + cA);
            }
#pragma unroll
            for (int ng = 0; ng < 4; ng++) {
                const int rowB = warp_n * 64 + ng * 16 + (lane & 7) + ((lane & 16) >> 1);
                const uint32_t cB = (uint32_t)((k0b + (((lane >> 3) & 1) << 4)) ^ ((rowB & 7) << 4));
                uint32_t B4[4];
                ldsm_x4(B4, st + SC_B + (uint32_t)(rowB * 128) + cB);
#pragma unroll
                for (int mt = 0; mt < 4; mt++) {
                    mma_bf16(acc[mt][ng * 2 + 0], Af[mt], B4 + 0);
                    mma_bf16(acc[mt][ng * 2 + 1], Af[mt], B4 + 2);
                }
            }
        }
        __syncthreads();
    }

    const int r0 = lane >> 2;
    const int c0 = (lane & 3) * 2;
#pragma unroll
    for (int mt = 0; mt < 4; mt++) {
        __nv_bfloat16* base = scoresb + ((size_t)bh * SS + i0 + warp_m * 64 + mt * 16 + r0) * SS
                                      + j0 + warp_n * 64 + c0;
#pragma unroll
        for (int nn = 0; nn < 8; nn++) {
            *(uint32_t*)(base + nn * 8) =
                pack2(__float2bfloat16(acc[mt][nn][0]), __float2bfloat16(acc[mt][nn][1]));
            *(uint32_t*)(base + 8 * SS + nn * 8) =
                pack2(__float2bfloat16(acc[mt][nn][2]), __float2bfloat16(acc[mt][nn][3]));
        }
    }
}

// ======================= fused softmax + PV (1-pass) =======================
#define FP_P  0                 // P: 128 rows x 256B = 32 KB
#define FP_V  32768             // V: 64 rows x 256B = 16 KB
#define FP_M  49152
#define FP_SC 49664
#define FP_L  50176
#define FP_SMEM 50688

__global__ __launch_bounds__(256)
void fused_pv_kernel(const __nv_bfloat16* __restrict__ scoresb, const float* __restrict__ cbt,
                     const __nv_bfloat16* __restrict__ vt, float* __restrict__ ctx)
{
    extern __shared__ __align__(1024) char sm[];
    const uint32_t sb = smem_to_u32(sm);
    float* sm_m  = (float*)(sm + FP_M);
    float* sm_sc = (float*)(sm + FP_SC);
    float* sm_l  = (float*)(sm + FP_L);

    const int tid = threadIdx.x;
    const int wid = tid >> 5;
    const int lane = tid & 31;
    const int bh = blockIdx.y;
    const int b = bh >> 4, h = bh & 15;
    const int i0 = blockIdx.x * 128;

    if (tid < 128) { sm_m[tid] = -INFINITY; sm_l[tid] = 0.f; }

    float acc[8][4];
#pragma unroll
    for (int nn = 0; nn < 8; nn++)
#pragma unroll
        for (int e = 0; e < 4; e++) acc[nn][e] = 0.f;

    const int srow = tid >> 1;
    const int sch = tid & 1;
    const __nv_bfloat16* sptr = scoresb + ((size_t)bh * SS + i0 + srow) * SS + sch * 64;
    const float* cptr = cbt + (size_t)bh * SS + sch * 64;

    const int m0 = wid * 16;
    const int r0 = m0 + (lane >> 2);
    const int r1 = r0 + 8;

    __syncthreads();

    for (int j0 = 0; j0 < SS; j0 += 128) {
        // V tile (single bf16): 64 rows x 16 chunks = 1024 chunks -> 4 iters
#pragma unroll
        for (int r = 0; r < 4; r++) {
            const int id = tid + 256 * r;
            const int row = id >> 4, cc = id & 15;
            const uint32_t so = (uint32_t)(row * 256 + ((cc * 16) ^ ((row & 7) << 4)));
            const size_t gi = ((size_t)bh * HEADV + row) * SS + j0 + cc * 8;
            cp16(sb + FP_V + so, vt + gi);
        }
        CP_COMMIT();

        float vals[64];
        float tmax = -INFINITY;
#pragma unroll
        for (int c8 = 0; c8 < 8; c8++) {
            uint4 u = *(const uint4*)(sptr + j0 + c8 * 8);
            float2 f0 = bf2_to_f2(u.x), f1 = bf2_to_f2(u.y);
            float2 f2 = bf2_to_f2(u.z), f3 = bf2_to_f2(u.w);
            float4 cb0 = *(const float4*)(cptr + j0 + c8 * 8);
            float4 cb1 = *(const float4*)(cptr + j0 + c8 * 8 + 4);
            vals[c8 * 8 + 0] = f0.x + cb0.x; vals[c8 * 8 + 1] = f0.y + cb0.y;
            vals[c8 * 8 + 2] = f1.x + cb0.z; vals[c8 * 8 + 3] = f1.y + cb0.w;
            vals[c8 * 8 + 4] = f2.x + cb1.x; vals[c8 * 8 + 5] = f2.y + cb1.y;
            vals[c8 * 8 + 6] = f3.x + cb1.z; vals[c8 * 8 + 7] = f3.y + cb1.w;
#pragma unroll
            for (int e = 0; e < 8; e++) tmax = fmaxf(tmax, vals[c8 * 8 + e]);
        }
        tmax = fmaxf(tmax, __shfl_xor_sync(0xffffffffu, tmax, 1));
        const float mold = sm_m[srow];
        const float mnew = fmaxf(mold, tmax);
        const float scl = __expf(mold - mnew);
        float rsum = 0.f;
#pragma unroll
        for (int c = 0; c < 64; c++) { vals[c] = __expf(vals[c] - mnew); rsum += vals[c]; }
        rsum += __shfl_xor_sync(0xffffffffu, rsum, 1);
        if (sch == 0) {
            sm_l[srow] = sm_l[srow] * scl + rsum;
            sm_m[srow] = mnew;
            sm_sc[srow] = scl;
        }
        // P store (single bf16)
#pragma unroll
        for (int c4 = 0; c4 < 16; c4++) {
            uint2 hp;
            hp.x = pack2(__float2bfloat16(vals[c4 * 4 + 0]), __float2bfloat16(vals[c4 * 4 + 1]));
            hp.y = pack2(__float2bfloat16(vals[c4 * 4 + 2]), __float2bfloat16(vals[c4 * 4 + 3]));
            const uint32_t colbyte = (uint32_t)(sch * 128 + c4 * 8);
            const uint32_t off = (uint32_t)(srow * 256) + (colbyte ^ ((srow & 7) << 4));
            *(uint2*)(sm + FP_P + off) = hp;
        }
        CP_WAIT0();
        __syncthreads();

        const float s0 = sm_sc[r0];
        const float s1 = sm_sc[r1];
#pragma unroll
        for (int nn = 0; nn < 8; nn++) {
            acc[nn][0] *= s0; acc[nn][1] *= s0;
            acc[nn][2] *= s1; acc[nn][3] *= s1;
        }
#pragma unroll
        for (int ks = 0; ks < 8; ks++) {
            const int k0b = ks * 32;
            uint32_t P4[4];
            const int rowa = m0 + (lane & 15);
            const uint32_t cA = (uint32_t)((k0b + ((lane >> 4) << 4)) ^ ((rowa & 7) << 4));
            ldsm_x4(P4, sb + FP_P + (uint32_t)(rowa * 256) + cA);
#pragma unroll
            for (int ng = 0; ng < 4; ng++) {
                const int rowb = ng * 16 + (lane & 7) + ((lane & 16) >> 1);
                const uint32_t cB = (uint32_t)((k0b + (((lane >> 3) & 1) << 4)) ^ ((rowb & 7) << 4));
                uint32_t V4[4];
                ldsm_x4(V4, sb + FP_V + (uint32_t)(rowb * 256) + cB);
                mma_bf16(acc[ng * 2 + 0], P4, V4 + 0);
                mma_bf16(acc[ng * 2 + 1], P4, V4 + 2);
            }
        }
        __syncthreads();
    }

    const float inv0 = 1.f / sm_l[r0];
    const float inv1 = 1.f / sm_l[r1];
    const int c0 = (lane & 3) * 2;
#pragma unroll
    for (int nn = 0; nn < 8; nn++) {
        const int col = h * HEADV + nn * 8 + c0;
        *(float2*)(ctx + ((size_t)b * SS + i0 + r0) * DVV + col) =
            make_float2(acc[nn][0] * inv0, acc[nn][1] * inv0);
        *(float2*)(ctx + ((size_t)b * SS + i0 + r1) * DVV + col) =
            make_float2(acc[nn][2] * inv1, acc[nn][3] * inv1);
    }
}

// ======================= LayerNorm =========================================
__global__ __launch_bounds__(256)
void ln_kernel(const float* __restrict__ res, const float* __restrict__ gamma,
               const float* __restrict__ beta, float* __restrict__ out)
{
    const int row = blockIdx.x;
    const int c = threadIdx.x * 4;
    const float4 v = *(const float4*)(res + (size_t)row * DOUT + c);
    float s  = v.x + v.y + v.z + v.w;
    float s2 = v.x * v.x + v.y * v.y + v.z * v.z + v.w * v.w;
#pragma unroll
    for (int o = 16; o >= 1; o >>= 1) {
        s  += __shfl_xor_sync(0xffffffffu, s,  o);
        s2 += __shfl_xor_sync(0xffffffffu, s2, o);
    }
    __shared__ float sh[8], sh2[8];
    __shared__ float mu_s, inv_s;
    const int w = threadIdx.x >> 5;
    if ((threadIdx.x & 31) == 0) { sh[w] = s; sh2[w] = s2; }
    __syncthreads();
    if (threadIdx.x == 0) {
        float S = 0.f, S2 = 0.f;
#pragma unroll
        for (int i = 0; i < 8; i++) { S += sh[i]; S2 += sh2[i]; }
        const float mu = S * (1.f / DOUT);
        const float var = S2 * (1.f / DOUT) - mu * mu;
        mu_s = mu; inv_s = rsqrtf(var + LN_EPS);
    }
    __syncthreads();
    const float mu = mu_s, inv = inv_s;
    const float4 g  = *(const float4*)(gamma + c);
    const float4 bt = *(const float4*)(beta + c);
    float4 o;
    o.x = (v.x - mu) * inv * g.x + bt.x;
    o.y = (v.y - mu) * inv * g.y + bt.y;
    o.z = (v.z - mu) * inv * g.z + bt.z;
    o.w = (v.w - mu) * inv * g.w + bt.w;
    *(float4*)(out + (size_t)row * DOUT + c) = o;
}

// ===========================================================================
extern "C" void kernel_launch(void* const* d_in, const int* in_sizes, int n_in,
                              void* d_out, int out_size)
{
    const float* x      = (const float*)d_in[0];
    const float* Wq     = (const float*)d_in[1];
    const float* Wk     = (const float*)d_in[2];
    const float* Wcb    = (const float*)d_in[3];
    const float* Wv     = (const float*)d_in[4];
    const float* bv     = (const float*)d_in[5];
    const float* mixing = (const float*)d_in[6];
    const float* Wd     = (const float*)d_in[7];
    const float* bd     = (const float*)d_in[8];
    const float* gamma  = (const float*)d_in[9];
    const float* beta   = (const float*)d_in[10];
    float* out = (float*)d_out;

    float *q, *k, *v, *ctx, *res, *cbt;
    __nv_bfloat16 *scoresb, *qm, *kb, *xb, *wb, *vt, *cxb;
    cudaGetSymbolAddress((void**)&q,       g_q);
    cudaGetSymbolAddress((void**)&k,       g_k);
    cudaGetSymbolAddress((void**)&v,       g_v);
    cudaGetSymbolAddress((void**)&ctx,     g_ctx);
    cudaGetSymbolAddress((void**)&res,     g_res);
    cudaGetSymbolAddress((void**)&cbt,     g_cbt);
    cudaGetSymbolAddress((void**)&scoresb, g_scoresb);
    cudaGetSymbolAddress((void**)&qm,      g_qm);
    cudaGetSymbolAddress((void**)&kb,      g_kb);
    cudaGetSymbolAddress((void**)&xb,      g_xb);
    cudaGetSymbolAddress((void**)&wb,      g_wb);
    cudaGetSymbolAddress((void**)&vt,      g_vt);
    cudaGetSymbolAddress((void**)&cxb,     g_cxb);

    cudaFuncSetAttribute(scores_kernel,   cudaFuncAttributeMaxDynamicSharedMemorySize, 2 * SC_STAGE);
    cudaFuncSetAttribute(hmma1_nt_kernel, cudaFuncAttributeMaxDynamicSharedMemorySize, 2 * P1_STAGE);
    cudaFuncSetAttribute(fused_pv_kernel, cudaFuncAttributeMaxDynamicSharedMemorySize, FP_SMEM);

    const size_t WSZ = 1024 * 1024;

    // converts (fp32 -> bf16)
    cvt_bf_kernel<<<MROWS * DIN / 1024, 256>>>(x, xb);
    cvt_bf_kernel<<<WSZ / 1024, 256>>>(Wq, wb + 0 * WSZ);
    cvt_bf_kernel<<<WSZ / 1024, 256>>>(Wk, wb + 1 * WSZ);
    cvt_bf_kernel<<<WSZ / 1024, 256>>>(Wv, wb + 2 * WSZ);
    cvt_bf_kernel<<<WSZ / 1024, 256>>>(Wd, wb + 3 * WSZ);

    // projections (1-pass bf16 HMMA)
    dim3 gProj(DKK / 128, MROWS / 128);    // (8, 32)
    hmma1_nt_kernel<<<gProj, 256, 2 * P1_STAGE>>>(xb, wb + 0 * WSZ, nullptr, nullptr, q, DKK);
    hmma1_nt_kernel<<<gProj, 256, 2 * P1_STAGE>>>(xb, wb + 1 * WSZ, nullptr, nullptr, k, DKK);
    hmma1_nt_kernel<<<gProj, 256, 2 * P1_STAGE>>>(xb, wb + 2 * WSZ, bv, nullptr, v, DVV);
    cb_kernel<<<MROWS / 16, 256>>>(x, Wcb, cbt);

    // attention preps
    cvt_bf_kernel<<<MROWS * DKK / 1024, 256>>>(k, kb);
    prep_q_kernel<<<dim3(SS * DKK / 4 / 256, BH), 256>>>(q, mixing, qm);
    prep_vt_kernel<<<dim3(SS / 64, HEADV / 16, BH), 256>>>(v, vt);

    // attention
    scores_kernel<<<dim3(SS / 256, SS / 128, BH), 256, 2 * SC_STAGE>>>(qm, kb, scoresb);
    fused_pv_kernel<<<dim3(SS / 128, BH), 256, FP_SMEM>>>(scoresb, cbt, vt, ctx);

    // output projection + residual + LN
    cvt_bf_kernel<<<MROWS * DVV / 1024, 256>>>(ctx, cxb);
    hmma1_nt_kernel<<<gProj, 256, 2 * P1_STAGE>>>(cxb, wb + 3 * WSZ, bd, x, res, DOUT);
    ln_kernel<<<MROWS, 256>>>(res, gamma, beta, out);
}